// round 1
// baseline (speedup 1.0000x reference)
#include <cuda_runtime.h>
#include <cstdint>
#include <math.h>

// ---------------- problem constants ----------------
#define BB 4
#define NN 4096
#define VV 2048
#define PP 32
#define CTOT 256          // concat channels: 16 + 48 + 80 + 112
#define YROWS 30
#define NBV (BB*VV)       // 8192

// ---------------- CG coefficient table (computed on device each launch) ----
__device__ float g_cg[3269];

// (j, l, J, offset) triples in a fixed order; offsets are cumulative sizes
__constant__ int c_tri[27][4] = {
  {1,1,0,0},{1,1,1,9},{1,1,2,36},
  {1,2,1,81},{1,2,2,126},{1,2,3,201},
  {1,3,2,306},{1,3,3,411},
  {2,1,1,558},{2,1,2,603},{2,1,3,678},
  {2,2,0,783},{2,2,1,808},{2,2,2,883},{2,2,3,1008},
  {2,3,1,1183},{2,3,2,1288},{2,3,3,1463},
  {3,1,2,1708},{3,1,3,1813},
  {3,2,1,1960},{3,2,2,2065},{3,2,3,2240},
  {3,3,0,2485},{3,3,1,2534},{3,3,2,2681},{3,3,3,2926}
};

__device__ __forceinline__ double dfact(int n){
  double r = 1.0;
  for(int i=2;i<=n;i++) r *= (double)i;
  return r;
}

__device__ double su2cg(int j1,int m1,int j2,int m2,int j3,int m3){
  if(m1+m2 != m3) return 0.0;
  int vmin = max(max(-j1+j2+m3, -j1+m1), 0);
  int vmax = min(min(j2+j3+m1, j3-j1+j2), j3+m3);
  double Cc = sqrt((double)(2*j3+1)*dfact(j3+j1-j2)*dfact(j3-j1+j2)*dfact(j1+j2-j3)
                   *dfact(j3+m3)*dfact(j3-m3)
                   /(dfact(j1+j2+j3+1)*dfact(j1-m1)*dfact(j1+m1)*dfact(j2-m2)*dfact(j2+m2)));
  double S = 0.0;
  for(int v=vmin; v<=vmax; v++){
    double t = dfact(j2+j3+m1-v)*dfact(j1-m1+v)
             /(dfact(v)*dfact(j3-j1+j2-v)*dfact(j3+m3-v)*dfact(v+j1-j2-m3));
    S += ((v+j2+m2)&1) ? -t : t;
  }
  return Cc*S;
}

// real->complex change-of-basis matrix for degree l (row-major (2l+1)x(2l+1))
__device__ void buildQ(int l, double2* q){
  int n = 2*l+1;
  for(int a=0;a<n*n;a++) q[a] = make_double2(0.0,0.0);
  const double s2 = 0.70710678118654752440;
  for(int m=-l;m<0;m++){
    q[(l+m)*n + (l-m)] = make_double2(s2, 0.0);
    q[(l+m)*n + (l+m)] = make_double2(0.0, -s2);
  }
  q[l*n+l] = make_double2(1.0,0.0);
  for(int m=1;m<=l;m++){
    double sg = (m&1)? -1.0 : 1.0;
    q[(l+m)*n + (l+m)] = make_double2(sg*s2, 0.0);
    q[(l+m)*n + (l-m)] = make_double2(0.0, sg*s2);
  }
  // multiply by (-i)^l
  int r = l & 3;
  double2 ph = (r==0)? make_double2(1,0) : (r==1)? make_double2(0,-1)
             : (r==2)? make_double2(-1,0) : make_double2(0,1);
  for(int a=0;a<n*n;a++){
    double2 v = q[a];
    q[a] = make_double2(ph.x*v.x - ph.y*v.y, ph.x*v.y + ph.y*v.x);
  }
}

__global__ void cg_setup_kernel(){
  __shared__ double2 Q1[49], Q2[49], Q3[49];
  __shared__ double Cs[343];
  int t = blockIdx.x;
  int j = c_tri[t][0], l = c_tri[t][1], J = c_tri[t][2], off = c_tri[t][3];
  int nj = 2*j+1, nl = 2*l+1, nJ = 2*J+1;
  int sz = nj*nl*nJ;

  if(threadIdx.x==0) buildQ(j, Q1);
  else if(threadIdx.x==1) buildQ(l, Q2);
  else if(threadIdx.x==2) buildQ(J, Q3);

  for(int idx=threadIdx.x; idx<sz; idx+=blockDim.x){
    int n  = idx % nJ;
    int rest = idx / nJ;
    int k  = rest % nl;
    int i  = rest / nl;
    Cs[idx] = su2cg(j, i-j, l, k-l, J, n-J);
  }
  __syncthreads();

  for(int idx=threadIdx.x; idx<sz; idx+=blockDim.x){
    int mm = idx % nJ;
    int rest = idx / nJ;
    int ll = rest % nl;
    int jj = rest / nl;
    double sx = 0.0;
    for(int i=0;i<nj;i++){
      double2 a = Q1[i*nj+jj];
      for(int k=0;k<nl;k++){
        int n = i + k - j - l + J;   // m3 = m1+m2 constraint
        if(n < 0 || n >= nJ) continue;
        double c = Cs[(i*nl+k)*nJ + n];
        if(c == 0.0) continue;
        double2 b  = Q2[k*nl+ll];
        double2 q3 = Q3[n*nJ+mm];    // use conj(q3)
        double2 ab = make_double2(a.x*b.x - a.y*b.y, a.x*b.y + a.y*b.x);
        sx += c * (ab.x*q3.x + ab.y*q3.y);
      }
    }
    g_cg[off+idx] = (float)sx;
  }
}

// ---------------- output layout tables ----------------
struct Seg { int kind, j, l, cstart, cgoff; };   // kind: 0 copy(l=0), 1 copy(j=0), 2 cg

__constant__ Seg c_segs[4][11] = {
  { // J=0 (CH=160)
    {0,0,0,0,0},{2,1,1,64,0},{2,2,2,112,783},{2,3,3,144,2485},
    {0,0,0,0,0},{0,0,0,0,0},{0,0,0,0,0},{0,0,0,0,0},{0,0,0,0,0},{0,0,0,0,0},{0,0,0,0,0}
  },
  { // J=1 (CH=336)
    {0,1,0,0,0},{1,0,1,48,0},{2,1,1,112,9},{2,2,1,160,558},{2,1,2,192,81},
    {2,2,2,240,808},{2,3,2,272,1960},{2,2,3,288,1183},{2,3,3,320,2534},
    {0,0,0,0,0},{0,0,0,0,0}
  },
  { // J=2 (CH=384)
    {0,2,0,0,0},{1,0,2,32,0},{2,1,1,96,36},{2,2,1,144,603},{2,3,1,176,1708},
    {2,1,2,192,126},{2,2,2,240,883},{2,3,2,272,2065},{2,1,3,288,306},
    {2,2,3,336,1288},{2,3,3,368,2681}
  },
  { // J=3 (CH=320)
    {0,3,0,0,0},{1,0,3,16,0},{2,2,1,80,678},{2,3,1,112,1813},{2,1,2,128,201},
    {2,2,2,176,1008},{2,3,2,208,2240},{2,1,3,224,411},{2,2,3,272,1463},
    {2,3,3,304,2926},{0,0,0,0,0}
  }
};

// chan/16 -> segment id
__constant__ unsigned char c_lut[4][24] = {
  {0,0,0,0,1,1,1,2,2,3, 0,0,0,0,0,0,0,0,0,0,0,0,0,0},
  {0,0,0,1,1,1,1,2,2,2,3,3,4,4,4,5,5,6,7,7,8, 0,0,0},
  {0,0,1,1,1,1,2,2,2,3,3,4,5,5,5,6,6,7,8,8,8,9,9,10},
  {0,1,1,1,1,2,2,3,4,4,4,5,5,6,7,7,7,8,8,9, 0,0,0,0}
};

__constant__ int c_yoff[4] = {0,4,13,23};
__constant__ int c_coff[4] = {0,16,64,144};
__constant__ int c_chj[4]  = {160,336,384,320};
__constant__ unsigned long long c_outoff[4] = {0ull, 1310720ull, 9568256ull, 25296896ull};

// ---------------- packed f32x2 fma ----------------
__device__ __forceinline__ unsigned long long ffma2(unsigned long long a,
                                                    unsigned long long b,
                                                    unsigned long long c){
  unsigned long long d;
  asm("fma.rn.f32x2 %0, %1, %2, %3;" : "=l"(d) : "l"(a), "l"(b), "l"(c));
  return d;
}

// ---------------- main fused kernel ----------------
__global__ void __launch_bounds__(128)
shconv_kernel(const float* __restrict__ x0, const float* __restrict__ x1,
              const float* __restrict__ x2, const float* __restrict__ x3,
              const int*  __restrict__ pidx, const float* __restrict__ kern,
              float* __restrict__ out)
{
  __shared__ int rowi[32];                 // (b*N + n) per patch
  __shared__ unsigned long long k2[960];   // kernel values duplicated as f32x2
  __shared__ float ysm[YROWS*CTOT];        // y[30][256]

  const int tid = threadIdx.x;
  const int bv  = blockIdx.x;

  if(tid < 32){
    int2 pr = ((const int2*)pidx)[(size_t)bv*PP + tid];
    rowi[tid] = pr.x * NN + pr.y;
  }
  const float* kb = kern + (size_t)bv * (PP*YROWS);
  for(int q=tid; q<PP*YROWS; q+=128){
    unsigned int u = __float_as_uint(kb[q]);
    k2[q] = ((unsigned long long)u << 32) | u;
  }
  __syncthreads();

  // ---- phase 1: y[30][256] = K[30x32] @ G[32x256], 2 channels per thread ----
  const int c = tid*2;
  const float* bp; int st;
  if(c < 16)       { bp = x0 + c;        st = 16;  }
  else if(c < 64)  { bp = x1 + (c-16);   st = 48;  }
  else if(c < 144) { bp = x2 + (c-64);   st = 80;  }
  else             { bp = x3 + (c-144);  st = 112; }

  unsigned long long acc[YROWS];
  #pragma unroll
  for(int y=0;y<YROWS;y++) acc[y] = 0ull;

  #pragma unroll 4
  for(int p=0;p<PP;p++){
    unsigned long long gv = *(const unsigned long long*)(bp + (size_t)rowi[p]*st);
    const unsigned long long* kp = &k2[p*YROWS];
    #pragma unroll
    for(int y=0;y<YROWS;y++)
      acc[y] = ffma2(kp[y], gv, acc[y]);
  }
  #pragma unroll
  for(int y=0;y<YROWS;y++)
    *(unsigned long long*)&ysm[y*CTOT + c] = acc[y];
  __syncthreads();

  // ---- phase 2: recombination + CG contraction, 2 output channels per item ----
  for(int idx = tid; idx < 2664; idx += 128){
    int J, p, cp;
    if(idx < 80)        { J=0; p=0; cp=idx; }
    else if(idx < 584)  { J=1; int r=idx-80;   p=r/168; cp=r-p*168; }
    else if(idx < 1544) { J=2; int r=idx-584;  p=r/192; cp=r-p*192; }
    else                { J=3; int r=idx-1544; p=r/160; cp=r-p*160; }
    int chan = cp << 1;
    Seg s = c_segs[J][c_lut[J][chan>>4]];
    int local = chan - s.cstart;
    int i2 = local >> 4;
    int ch = local & 15;

    float rx, ry;
    if(s.kind == 0){
      int row = c_yoff[s.j] + p*(4-s.j) + i2;
      float2 v = *(const float2*)&ysm[row*CTOT + ch];
      rx = v.x; ry = v.y;
    } else if(s.kind == 1){
      float2 v = *(const float2*)&ysm[i2*CTOT + c_coff[s.l] + p*16 + ch];
      rx = v.x; ry = v.y;
    } else {
      const int sj = s.j, sl = s.l;
      const int nl = 2*sl+1, nJ = 2*J+1;
      rx = 0.f; ry = 0.f;
      int cgbase = s.cgoff + p;
      for(int n=0; n<=2*sj; n++){
        const float* yp = &ysm[(c_yoff[sj] + n*(4-sj) + i2)*CTOT + c_coff[sl] + ch];
        int cgrow = cgbase + n*nl*nJ;
        #pragma unroll 1
        for(int m=0; m<nl; m++){
          float cf = __ldg(&g_cg[cgrow + m*nJ]);
          float2 yv = *(const float2*)(yp + m*16);
          rx = fmaf(cf, yv.x, rx);
          ry = fmaf(cf, yv.y, ry);
        }
      }
    }
    size_t o = (size_t)c_outoff[J] + ((size_t)bv*(2*J+1) + p)*(size_t)c_chj[J] + chan;
    *(float2*)(out + o) = make_float2(rx, ry);
  }
}

// ---------------- launch ----------------
extern "C" void kernel_launch(void* const* d_in, const int* in_sizes, int n_in,
                              void* d_out, int out_size)
{
  const float* x0   = (const float*)d_in[0];
  const float* x1   = (const float*)d_in[1];
  const float* x2   = (const float*)d_in[2];
  const float* x3   = (const float*)d_in[3];
  const int*   pidx = (const int*)  d_in[4];
  const float* kern = (const float*)d_in[5];
  float* out = (float*)d_out;

  cg_setup_kernel<<<27, 256>>>();
  shconv_kernel<<<NBV, 128>>>(x0, x1, x2, x3, pidx, kern, out);
}

// round 2
// speedup vs baseline: 1.9266x; 1.9266x over previous
#include <cuda_runtime.h>
#include <cstdint>
#include <math.h>

// ---------------- problem constants ----------------
#define BB 4
#define NN 4096
#define VV 2048
#define PP 32
#define CTOT 256          // concat channels: 16 + 48 + 80 + 112
#define YROWS 30
#define NBV (BB*VV)       // 8192

// ---------------- CG coefficient table (computed on device each launch) ----
__device__ float g_cg[3269];

// sparse program tables (built on device each launch)
__device__ unsigned long long g_terms[3400];   // {low32: coeff bits, high32: ysm delta}
__device__ unsigned long long g_items[2664];   // packed headers
__device__ int g_lstart[160];
__device__ int g_lcount[160];

// (j, l, J, offset) triples in a fixed order; offsets are cumulative sizes
__constant__ int c_tri[27][4] = {
  {1,1,0,0},{1,1,1,9},{1,1,2,36},
  {1,2,1,81},{1,2,2,126},{1,2,3,201},
  {1,3,2,306},{1,3,3,411},
  {2,1,1,558},{2,1,2,603},{2,1,3,678},
  {2,2,0,783},{2,2,1,808},{2,2,2,883},{2,2,3,1008},
  {2,3,1,1183},{2,3,2,1288},{2,3,3,1463},
  {3,1,2,1708},{3,1,3,1813},
  {3,2,1,1960},{3,2,2,2065},{3,2,3,2240},
  {3,3,0,2485},{3,3,1,2534},{3,3,2,2681},{3,3,3,2926}
};

__device__ __forceinline__ double dfact(int n){
  double r = 1.0;
  for(int i=2;i<=n;i++) r *= (double)i;
  return r;
}

__device__ double su2cg(int j1,int m1,int j2,int m2,int j3,int m3){
  if(m1+m2 != m3) return 0.0;
  int vmin = max(max(-j1+j2+m3, -j1+m1), 0);
  int vmax = min(min(j2+j3+m1, j3-j1+j2), j3+m3);
  double Cc = sqrt((double)(2*j3+1)*dfact(j3+j1-j2)*dfact(j3-j1+j2)*dfact(j1+j2-j3)
                   *dfact(j3+m3)*dfact(j3-m3)
                   /(dfact(j1+j2+j3+1)*dfact(j1-m1)*dfact(j1+m1)*dfact(j2-m2)*dfact(j2+m2)));
  double S = 0.0;
  for(int v=vmin; v<=vmax; v++){
    double t = dfact(j2+j3+m1-v)*dfact(j1-m1+v)
             /(dfact(v)*dfact(j3-j1+j2-v)*dfact(j3+m3-v)*dfact(v+j1-j2-m3));
    S += ((v+j2+m2)&1) ? -t : t;
  }
  return Cc*S;
}

__device__ void buildQ(int l, double2* q){
  int n = 2*l+1;
  for(int a=0;a<n*n;a++) q[a] = make_double2(0.0,0.0);
  const double s2 = 0.70710678118654752440;
  for(int m=-l;m<0;m++){
    q[(l+m)*n + (l-m)] = make_double2(s2, 0.0);
    q[(l+m)*n + (l+m)] = make_double2(0.0, -s2);
  }
  q[l*n+l] = make_double2(1.0,0.0);
  for(int m=1;m<=l;m++){
    double sg = (m&1)? -1.0 : 1.0;
    q[(l+m)*n + (l+m)] = make_double2(sg*s2, 0.0);
    q[(l+m)*n + (l-m)] = make_double2(0.0, sg*s2);
  }
  int r = l & 3;
  double2 ph = (r==0)? make_double2(1,0) : (r==1)? make_double2(0,-1)
             : (r==2)? make_double2(-1,0) : make_double2(0,1);
  for(int a=0;a<n*n;a++){
    double2 v = q[a];
    q[a] = make_double2(ph.x*v.x - ph.y*v.y, ph.x*v.y + ph.y*v.x);
  }
}

__global__ void cg_setup_kernel(){
  __shared__ double2 Q1[49], Q2[49], Q3[49];
  __shared__ double Cs[343];
  int t = blockIdx.x;
  int j = c_tri[t][0], l = c_tri[t][1], J = c_tri[t][2], off = c_tri[t][3];
  int nj = 2*j+1, nl = 2*l+1, nJ = 2*J+1;
  int sz = nj*nl*nJ;

  if(threadIdx.x==0) buildQ(j, Q1);
  else if(threadIdx.x==1) buildQ(l, Q2);
  else if(threadIdx.x==2) buildQ(J, Q3);

  for(int idx=threadIdx.x; idx<sz; idx+=blockDim.x){
    int n  = idx % nJ;
    int rest = idx / nJ;
    int k  = rest % nl;
    int i  = rest / nl;
    Cs[idx] = su2cg(j, i-j, l, k-l, J, n-J);
  }
  __syncthreads();

  for(int idx=threadIdx.x; idx<sz; idx+=blockDim.x){
    int mm = idx % nJ;
    int rest = idx / nJ;
    int ll = rest % nl;
    int jj = rest / nl;
    double sx = 0.0;
    for(int i=0;i<nj;i++){
      double2 a = Q1[i*nj+jj];
      for(int k=0;k<nl;k++){
        int n = i + k - j - l + J;
        if(n < 0 || n >= nJ) continue;
        double c = Cs[(i*nl+k)*nJ + n];
        if(c == 0.0) continue;
        double2 b  = Q2[k*nl+ll];
        double2 q3 = Q3[n*nJ+mm];
        double2 ab = make_double2(a.x*b.x - a.y*b.y, a.x*b.y + a.y*b.x);
        sx += c * (ab.x*q3.x + ab.y*q3.y);
      }
    }
    g_cg[off+idx] = (float)sx;
  }
}

// ---------------- output layout tables ----------------
struct Seg { int kind, j, l, cstart, cgoff; };

__constant__ Seg c_segs[4][11] = {
  { {0,0,0,0,0},{2,1,1,64,0},{2,2,2,112,783},{2,3,3,144,2485},
    {0,0,0,0,0},{0,0,0,0,0},{0,0,0,0,0},{0,0,0,0,0},{0,0,0,0,0},{0,0,0,0,0},{0,0,0,0,0} },
  { {0,1,0,0,0},{1,0,1,48,0},{2,1,1,112,9},{2,2,1,160,558},{2,1,2,192,81},
    {2,2,2,240,808},{2,3,2,272,1960},{2,2,3,288,1183},{2,3,3,320,2534},
    {0,0,0,0,0},{0,0,0,0,0} },
  { {0,2,0,0,0},{1,0,2,32,0},{2,1,1,96,36},{2,2,1,144,603},{2,3,1,176,1708},
    {2,1,2,192,126},{2,2,2,240,883},{2,3,2,272,2065},{2,1,3,288,306},
    {2,2,3,336,1288},{2,3,3,368,2681} },
  { {0,3,0,0,0},{1,0,3,16,0},{2,2,1,80,678},{2,3,1,112,1813},{2,1,2,128,201},
    {2,2,2,176,1008},{2,3,2,208,2240},{2,1,3,224,411},{2,2,3,272,1463},
    {2,3,3,304,2926},{0,0,0,0,0} }
};

__constant__ unsigned char c_lut[4][24] = {
  {0,0,0,0,1,1,1,2,2,3, 0,0,0,0,0,0,0,0,0,0,0,0,0,0},
  {0,0,0,1,1,1,1,2,2,2,3,3,4,4,4,5,5,6,7,7,8, 0,0,0},
  {0,0,1,1,1,1,2,2,2,3,3,4,5,5,5,6,6,7,8,8,8,9,9,10},
  {0,1,1,1,1,2,2,3,4,4,4,5,5,6,7,7,7,8,8,9, 0,0,0,0}
};

__constant__ int c_yoff[4] = {0,4,13,23};
__constant__ int c_coff[4] = {0,16,64,144};
__constant__ int c_chj[4]  = {160,336,384,320};
__constant__ unsigned long long c_outoff[4] = {0ull, 1310720ull, 9568256ull, 25296896ull};
__constant__ int c_bvmul[4] = {160, 1008, 1920, 2240};
__constant__ int c_jb[4] = {0,1,4,9};   // cumulative (2j+1)

// ---------------- sparse program builder ----------------
__global__ void table_build(){
  int tid = threadIdx.x;

  // ---- pass A: per-list nonzero counts ----
  if(tid < 157){
    if(tid < 125){
      int k = tid, t = 0;
      for(; t < 27; t++){ int sz = 2*c_tri[t][2]+1; if(k < sz) break; k -= sz; }
      int j = c_tri[t][0], l = c_tri[t][1], J = c_tri[t][2], off = c_tri[t][3];
      int nl = 2*l+1, nJ = 2*J+1, p = k;
      int cnt = 0;
      for(int n = 0; n <= 2*j; n++)
        for(int m = 0; m < nl; m++)
          if(fabsf(g_cg[off + (n*nl+m)*nJ + p]) > 1e-6f) cnt++;
      g_lcount[tid] = cnt;
    } else {
      g_lcount[tid] = 1;
    }
  }
  __syncthreads();
  if(tid == 0){
    int s = 0;
    for(int i = 0; i < 157; i++){ g_lstart[i] = s; s += g_lcount[i]; }
  }
  __syncthreads();

  // ---- pass B: write terms ----
  if(tid < 157){
    int st = g_lstart[tid];
    if(tid < 125){
      int k = tid, t = 0;
      for(; t < 27; t++){ int sz = 2*c_tri[t][2]+1; if(k < sz) break; k -= sz; }
      int j = c_tri[t][0], l = c_tri[t][1], J = c_tri[t][2], off = c_tri[t][3];
      int nl = 2*l+1, nJ = 2*J+1, p = k;
      for(int n = 0; n <= 2*j; n++)
        for(int m = 0; m < nl; m++){
          float c = g_cg[off + (n*nl+m)*nJ + p];
          if(fabsf(c) > 1e-6f){
            int delta = n*(4-j)*CTOT + m*16;
            g_terms[st++] = ((unsigned long long)(unsigned)delta << 32) | __float_as_uint(c);
          }
        }
    } else if(tid < 141){
      // l=0 copy into out[j]: id = 125 + jb[j] + p
      int k = tid - 125, j = 0;
      while(k >= 2*j+1){ k -= 2*j+1; j++; }
      int delta = k*(4-j)*CTOT;
      g_terms[st] = ((unsigned long long)(unsigned)delta << 32) | __float_as_uint(1.0f);
    } else {
      // j=0 copy into out[l]: id = 141 + jb[l] + p
      int k = tid - 141, l = 0;
      while(k >= 2*l+1){ k -= 2*l+1; l++; }
      int delta = k*16;
      g_terms[st] = ((unsigned long long)(unsigned)delta << 32) | __float_as_uint(1.0f);
    }
  }
  __syncthreads();

  // ---- pass C: item headers ----
  for(int idx = tid; idx < 2664; idx += blockDim.x){
    int J, p, cp;
    if(idx < 80)        { J=0; p=0; cp=idx; }
    else if(idx < 584)  { J=1; int r=idx-80;   p=r/168; cp=r-p*168; }
    else if(idx < 1544) { J=2; int r=idx-584;  p=r/192; cp=r-p*192; }
    else                { J=3; int r=idx-1544; p=r/160; cp=r-p*160; }
    int chan = cp << 1;
    Seg s = c_segs[J][c_lut[J][chan>>4]];
    int local = chan - s.cstart;
    int i2 = local >> 4;
    int ch = local & 15;

    int lid;
    if(s.kind == 0)      lid = 125 + c_jb[s.j] + p;
    else if(s.kind == 1) lid = 141 + c_jb[s.l] + p;
    else {
      int t = 0;
      for(; t < 27; t++) if(c_tri[t][3] == s.cgoff) break;
      int base = 0;
      for(int q = 0; q < t; q++) base += 2*c_tri[q][2]+1;
      lid = base + p;
    }
    int ybase = (c_yoff[s.j] + i2)*CTOT + c_coff[s.l] + ch;
    int start = g_lstart[lid];
    int cnt   = g_lcount[lid];
    unsigned long long outb = c_outoff[J] + (unsigned long long)p*c_chj[J] + chan;
    unsigned long long h = (unsigned long long)ybase
                         | ((unsigned long long)cnt   << 13)
                         | ((unsigned long long)start << 19)
                         | ((unsigned long long)J     << 31)
                         | (outb << 33);
    g_items[idx] = h;
  }
}

// ---------------- packed f32x2 ops ----------------
__device__ __forceinline__ unsigned long long ffma2(unsigned long long a,
                                                    unsigned long long b,
                                                    unsigned long long c){
  unsigned long long d;
  asm("fma.rn.f32x2 %0, %1, %2, %3;" : "=l"(d) : "l"(a), "l"(b), "l"(c));
  return d;
}
__device__ __forceinline__ unsigned long long fadd2(unsigned long long a,
                                                    unsigned long long b){
  unsigned long long d;
  asm("add.rn.f32x2 %0, %1, %2;" : "=l"(d) : "l"(a), "l"(b));
  return d;
}
__device__ __forceinline__ unsigned long long dup2(unsigned int v){
  unsigned long long d;
  asm("mov.b64 %0, {%1, %1};" : "=l"(d) : "r"(v));
  return d;
}

// ---------------- main fused kernel ----------------
// k2 layout: [p][48] u64 slots; rows 0..14 at slots 0..14, rows 15..29 at 16..30
__global__ void __launch_bounds__(128)
shconv_kernel(const float* __restrict__ x0, const float* __restrict__ x1,
              const float* __restrict__ x2, const float* __restrict__ x3,
              const int*  __restrict__ pidx, const float* __restrict__ kern,
              float* __restrict__ out)
{
  __shared__ int rowi[32];
  __shared__ __align__(16) unsigned long long k2[32*48];
  __shared__ __align__(16) float ysm[YROWS*CTOT];

  const int tid = threadIdx.x;
  const int bv  = blockIdx.x;

  if(tid < 32){
    int2 pr = ((const int2*)pidx)[(size_t)bv*PP + tid];
    rowi[tid] = pr.x * NN + pr.y;
  }
  const float* kb = kern + (size_t)bv * (PP*YROWS);
  for(int q = tid; q < 32*48; q += 128){
    int p = q / 48, s = q - p*48;
    int row = (s < 16) ? s : s - 1;         // slot 15 and 31..47 are pads
    float v = (s != 15 && row < 30) ? kb[p*YROWS + row] : 0.f;
    unsigned int u = __float_as_uint(v);
    k2[q] = ((unsigned long long)u << 32) | u;
  }
  __syncthreads();

  // ---- phase 1: y[30][256] = K[30x32] @ G[32x256] ----
  // thread = (half: 15 rows) x (cq: 4 channels)
  const int cq = tid & 63;
  const int half = tid >> 6;
  const int c = cq * 4;
  const float* bp; int st;
  if(c < 16)       { bp = x0 + c;        st = 16;  }
  else if(c < 64)  { bp = x1 + (c-16);   st = 48;  }
  else if(c < 144) { bp = x2 + (c-64);   st = 80;  }
  else             { bp = x3 + (c-144);  st = 112; }

  unsigned long long acc0[15], acc1[15];
  #pragma unroll
  for(int y = 0; y < 15; y++){ acc0[y] = 0ull; acc1[y] = 0ull; }

  ulonglong2 gv = *(const ulonglong2*)(bp + (size_t)rowi[0]*st);
  #pragma unroll 4
  for(int p = 0; p < PP; p++){
    ulonglong2 nx = *(const ulonglong2*)(bp + (size_t)rowi[(p+1)&31]*st);
    const unsigned long long* kp = &k2[p*48 + half*16];
    #pragma unroll
    for(int y = 0; y < 15; y++){
      unsigned long long kv = kp[y];
      acc0[y] = ffma2(kv, gv.x, acc0[y]);
      acc1[y] = ffma2(kv, gv.y, acc1[y]);
    }
    gv = nx;
  }
  #pragma unroll
  for(int y = 0; y < 15; y++){
    int row = half*15 + y;
    ulonglong2 v; v.x = acc0[y]; v.y = acc1[y];
    *(ulonglong2*)&ysm[row*CTOT + c] = v;
  }
  __syncthreads();

  // ---- phase 2: sparse CG program ----
  for(int idx = tid; idx < 2664; idx += 128){
    unsigned long long h = __ldg(&g_items[idx]);
    int ybase = (int)(h & 0x1FFF);
    int cnt   = (int)((h >> 13) & 63);
    int start = (int)((h >> 19) & 4095);
    int J     = (int)((h >> 31) & 3);
    unsigned long long outb = h >> 33;

    unsigned long long a0 = 0ull, a1 = 0ull;
    const unsigned long long* tp = &g_terms[start];
    int t = 0;
    for(; t + 2 <= cnt; t += 2){
      unsigned long long t0 = __ldg(&tp[t]);
      unsigned long long t1 = __ldg(&tp[t+1]);
      unsigned long long y0 = *(const unsigned long long*)&ysm[ybase + (int)(t0 >> 32)];
      unsigned long long y1 = *(const unsigned long long*)&ysm[ybase + (int)(t1 >> 32)];
      a0 = ffma2(dup2((unsigned int)t0), y0, a0);
      a1 = ffma2(dup2((unsigned int)t1), y1, a1);
    }
    if(t < cnt){
      unsigned long long t0 = __ldg(&tp[t]);
      unsigned long long y0 = *(const unsigned long long*)&ysm[ybase + (int)(t0 >> 32)];
      a0 = ffma2(dup2((unsigned int)t0), y0, a0);
    }
    unsigned long long r = fadd2(a0, a1);
    size_t o = (size_t)outb + (size_t)bv * (size_t)c_bvmul[J];
    *(unsigned long long*)(out + o) = r;
  }
}

// ---------------- launch ----------------
extern "C" void kernel_launch(void* const* d_in, const int* in_sizes, int n_in,
                              void* d_out, int out_size)
{
  const float* x0   = (const float*)d_in[0];
  const float* x1   = (const float*)d_in[1];
  const float* x2   = (const float*)d_in[2];
  const float* x3   = (const float*)d_in[3];
  const int*   pidx = (const int*)  d_in[4];
  const float* kern = (const float*)d_in[5];
  float* out = (float*)d_out;

  cg_setup_kernel<<<27, 256>>>();
  table_build<<<1, 256>>>();
  shconv_kernel<<<NBV, 128>>>(x0, x1, x2, x3, pidx, kern, out);
}

// round 3
// speedup vs baseline: 2.5254x; 1.3108x over previous
#include <cuda_runtime.h>
#include <cstdint>
#include <math.h>

// ---------------- problem constants ----------------
#define BB 4
#define NN 4096
#define PP 32
#define CTOT 256
#define YROWS 30
#define NBV (BB*2048)

// ---------------- device tables ----------------
__device__ float g_cg[3269];
__device__ unsigned long long g_terms[3400];
__device__ unsigned long long g_items[2664];
__device__ int g_lstart[160];
__device__ int g_lcount[160];

__constant__ int c_tri[27][4] = {
  {1,1,0,0},{1,1,1,9},{1,1,2,36},
  {1,2,1,81},{1,2,2,126},{1,2,3,201},
  {1,3,2,306},{1,3,3,411},
  {2,1,1,558},{2,1,2,603},{2,1,3,678},
  {2,2,0,783},{2,2,1,808},{2,2,2,883},{2,2,3,1008},
  {2,3,1,1183},{2,3,2,1288},{2,3,3,1463},
  {3,1,2,1708},{3,1,3,1813},
  {3,2,1,1960},{3,2,2,2065},{3,2,3,2240},
  {3,3,0,2485},{3,3,1,2534},{3,3,2,2681},{3,3,3,2926}
};

// exact factorials 0..20 in double
__constant__ double c_fact[21] = {
  1.0,1.0,2.0,6.0,24.0,120.0,720.0,5040.0,40320.0,362880.0,3628800.0,
  39916800.0,479001600.0,6227020800.0,87178291200.0,1307674368000.0,
  20922789888000.0,355687428096000.0,6402373705728000.0,
  121645100408832000.0,2432902008176640000.0
};

__device__ __forceinline__ double dfact(int n){ return c_fact[n]; }

__device__ double su2cg(int j1,int m1,int j2,int m2,int j3,int m3){
  if(m1+m2 != m3) return 0.0;
  int vmin = max(max(-j1+j2+m3, -j1+m1), 0);
  int vmax = min(min(j2+j3+m1, j3-j1+j2), j3+m3);
  double Cc = sqrt((double)(2*j3+1)*dfact(j3+j1-j2)*dfact(j3-j1+j2)*dfact(j1+j2-j3)
                   *dfact(j3+m3)*dfact(j3-m3)
                   /(dfact(j1+j2+j3+1)*dfact(j1-m1)*dfact(j1+m1)*dfact(j2-m2)*dfact(j2+m2)));
  double S = 0.0;
  for(int v=vmin; v<=vmax; v++){
    double t = dfact(j2+j3+m1-v)*dfact(j1-m1+v)
             /(dfact(v)*dfact(j3-j1+j2-v)*dfact(j3+m3-v)*dfact(v+j1-j2-m3));
    S += ((v+j2+m2)&1) ? -t : t;
  }
  return Cc*S;
}

__device__ void buildQ(int l, double2* q){
  int n = 2*l+1;
  for(int a=0;a<n*n;a++) q[a] = make_double2(0.0,0.0);
  const double s2 = 0.70710678118654752440;
  for(int m=-l;m<0;m++){
    q[(l+m)*n + (l-m)] = make_double2(s2, 0.0);
    q[(l+m)*n + (l+m)] = make_double2(0.0, -s2);
  }
  q[l*n+l] = make_double2(1.0,0.0);
  for(int m=1;m<=l;m++){
    double sg = (m&1)? -1.0 : 1.0;
    q[(l+m)*n + (l+m)] = make_double2(sg*s2, 0.0);
    q[(l+m)*n + (l-m)] = make_double2(0.0, sg*s2);
  }
  int r = l & 3;
  double2 ph = (r==0)? make_double2(1,0) : (r==1)? make_double2(0,-1)
             : (r==2)? make_double2(-1,0) : make_double2(0,1);
  for(int a=0;a<n*n;a++){
    double2 v = q[a];
    q[a] = make_double2(ph.x*v.x - ph.y*v.y, ph.x*v.y + ph.y*v.x);
  }
}

__global__ void cg_setup_kernel(){
  __shared__ double2 Q1[49], Q2[49], Q3[49];
  __shared__ double Cs[343];
  int t = blockIdx.x;
  int j = c_tri[t][0], l = c_tri[t][1], J = c_tri[t][2], off = c_tri[t][3];
  int nj = 2*j+1, nl = 2*l+1, nJ = 2*J+1;
  int sz = nj*nl*nJ;

  if(threadIdx.x==0) buildQ(j, Q1);
  else if(threadIdx.x==1) buildQ(l, Q2);
  else if(threadIdx.x==2) buildQ(J, Q3);

  for(int idx=threadIdx.x; idx<sz; idx+=blockDim.x){
    int n  = idx % nJ;
    int rest = idx / nJ;
    int k  = rest % nl;
    int i  = rest / nl;
    Cs[idx] = su2cg(j, i-j, l, k-l, J, n-J);
  }
  __syncthreads();

  for(int idx=threadIdx.x; idx<sz; idx+=blockDim.x){
    int mm = idx % nJ;
    int rest = idx / nJ;
    int ll = rest % nl;
    int jj = rest / nl;
    double sx = 0.0;
    for(int i=0;i<nj;i++){
      double2 a = Q1[i*nj+jj];
      for(int k=0;k<nl;k++){
        int n = i + k - j - l + J;
        if(n < 0 || n >= nJ) continue;
        double c = Cs[(i*nl+k)*nJ + n];
        if(c == 0.0) continue;
        double2 b  = Q2[k*nl+ll];
        double2 q3 = Q3[n*nJ+mm];
        double2 ab = make_double2(a.x*b.x - a.y*b.y, a.x*b.y + a.y*b.x);
        sx += c * (ab.x*q3.x + ab.y*q3.y);
      }
    }
    g_cg[off+idx] = (float)sx;
  }
}

// ---------------- output layout tables ----------------
struct Seg { int kind, j, l, cstart, cgoff; };

__constant__ Seg c_segs[4][11] = {
  { {0,0,0,0,0},{2,1,1,64,0},{2,2,2,112,783},{2,3,3,144,2485},
    {0,0,0,0,0},{0,0,0,0,0},{0,0,0,0,0},{0,0,0,0,0},{0,0,0,0,0},{0,0,0,0,0},{0,0,0,0,0} },
  { {0,1,0,0,0},{1,0,1,48,0},{2,1,1,112,9},{2,2,1,160,558},{2,1,2,192,81},
    {2,2,2,240,808},{2,3,2,272,1960},{2,2,3,288,1183},{2,3,3,320,2534},
    {0,0,0,0,0},{0,0,0,0,0} },
  { {0,2,0,0,0},{1,0,2,32,0},{2,1,1,96,36},{2,2,1,144,603},{2,3,1,176,1708},
    {2,1,2,192,126},{2,2,2,240,883},{2,3,2,272,2065},{2,1,3,288,306},
    {2,2,3,336,1288},{2,3,3,368,2681} },
  { {0,3,0,0,0},{1,0,3,16,0},{2,2,1,80,678},{2,3,1,112,1813},{2,1,2,128,201},
    {2,2,2,176,1008},{2,3,2,208,2240},{2,1,3,224,411},{2,2,3,272,1463},
    {2,3,3,304,2926},{0,0,0,0,0} }
};

__constant__ unsigned char c_lut[4][24] = {
  {0,0,0,0,1,1,1,2,2,3, 0,0,0,0,0,0,0,0,0,0,0,0,0,0},
  {0,0,0,1,1,1,1,2,2,2,3,3,4,4,4,5,5,6,7,7,8, 0,0,0},
  {0,0,1,1,1,1,2,2,2,3,3,4,5,5,5,6,6,7,8,8,8,9,9,10},
  {0,1,1,1,1,2,2,3,4,4,4,5,5,6,7,7,7,8,8,9, 0,0,0,0}
};

__constant__ int c_yoff[4] = {0,4,13,23};
__constant__ int c_coff[4] = {0,16,64,144};
__constant__ int c_chj[4]  = {160,336,384,320};
__constant__ unsigned long long c_outoff[4] = {0ull, 1310720ull, 9568256ull, 25296896ull};
__constant__ int c_bvmul[4] = {160, 1008, 1920, 2240};
__constant__ int c_jb[4] = {0,1,4,9};

// ---------------- sparse program builder ----------------
__global__ void table_build(){
  int tid = threadIdx.x;

  if(tid < 157){
    if(tid < 125){
      int k = tid, t = 0;
      for(; t < 27; t++){ int sz = 2*c_tri[t][2]+1; if(k < sz) break; k -= sz; }
      int j = c_tri[t][0], l = c_tri[t][1], J = c_tri[t][2], off = c_tri[t][3];
      int nl = 2*l+1, nJ = 2*J+1, p = k;
      int cnt = 0;
      for(int n = 0; n <= 2*j; n++)
        for(int m = 0; m < nl; m++)
          if(fabsf(g_cg[off + (n*nl+m)*nJ + p]) > 1e-6f) cnt++;
      g_lcount[tid] = cnt;
    } else {
      g_lcount[tid] = 1;
    }
  }
  __syncthreads();
  if(tid == 0){
    int s = 0;
    for(int i = 0; i < 157; i++){ g_lstart[i] = s; s += g_lcount[i]; }
  }
  __syncthreads();

  if(tid < 157){
    int st = g_lstart[tid];
    if(tid < 125){
      int k = tid, t = 0;
      for(; t < 27; t++){ int sz = 2*c_tri[t][2]+1; if(k < sz) break; k -= sz; }
      int j = c_tri[t][0], l = c_tri[t][1], J = c_tri[t][2], off = c_tri[t][3];
      int nl = 2*l+1, nJ = 2*J+1, p = k;
      for(int n = 0; n <= 2*j; n++)
        for(int m = 0; m < nl; m++){
          float c = g_cg[off + (n*nl+m)*nJ + p];
          if(fabsf(c) > 1e-6f){
            int delta = n*(4-j)*CTOT + m*16;
            g_terms[st++] = ((unsigned long long)(unsigned)delta << 32) | __float_as_uint(c);
          }
        }
    } else if(tid < 141){
      int k = tid - 125, j = 0;
      while(k >= 2*j+1){ k -= 2*j+1; j++; }
      int delta = k*(4-j)*CTOT;
      g_terms[st] = ((unsigned long long)(unsigned)delta << 32) | __float_as_uint(1.0f);
    } else {
      int k = tid - 141, l = 0;
      while(k >= 2*l+1){ k -= 2*l+1; l++; }
      int delta = k*16;
      g_terms[st] = ((unsigned long long)(unsigned)delta << 32) | __float_as_uint(1.0f);
    }
  }
  __syncthreads();

  for(int idx = tid; idx < 2664; idx += blockDim.x){
    int J, p, cp;
    if(idx < 80)        { J=0; p=0; cp=idx; }
    else if(idx < 584)  { J=1; int r=idx-80;   p=r/168; cp=r-p*168; }
    else if(idx < 1544) { J=2; int r=idx-584;  p=r/192; cp=r-p*192; }
    else                { J=3; int r=idx-1544; p=r/160; cp=r-p*160; }
    int chan = cp << 1;
    Seg s = c_segs[J][c_lut[J][chan>>4]];
    int local = chan - s.cstart;
    int i2 = local >> 4;
    int ch = local & 15;

    int lid;
    if(s.kind == 0)      lid = 125 + c_jb[s.j] + p;
    else if(s.kind == 1) lid = 141 + c_jb[s.l] + p;
    else {
      int t = 0;
      for(; t < 27; t++) if(c_tri[t][3] == s.cgoff) break;
      int base = 0;
      for(int q = 0; q < t; q++) base += 2*c_tri[q][2]+1;
      lid = base + p;
    }
    int ybase = (c_yoff[s.j] + i2)*CTOT + c_coff[s.l] + ch;
    int start = g_lstart[lid];
    int cnt   = g_lcount[lid];
    unsigned long long outb = c_outoff[J] + (unsigned long long)p*c_chj[J] + chan;
    unsigned long long h = (unsigned long long)ybase
                         | ((unsigned long long)cnt   << 13)
                         | ((unsigned long long)start << 19)
                         | ((unsigned long long)J     << 31)
                         | (outb << 33);
    g_items[idx] = h;
  }
}

// ---------------- packed f32x2 ops ----------------
__device__ __forceinline__ unsigned long long ffma2(unsigned long long a,
                                                    unsigned long long b,
                                                    unsigned long long c){
  unsigned long long d;
  asm("fma.rn.f32x2 %0, %1, %2, %3;" : "=l"(d) : "l"(a), "l"(b), "l"(c));
  return d;
}
__device__ __forceinline__ unsigned long long fadd2(unsigned long long a,
                                                    unsigned long long b){
  unsigned long long d;
  asm("add.rn.f32x2 %0, %1, %2;" : "=l"(d) : "l"(a), "l"(b));
  return d;
}
__device__ __forceinline__ unsigned long long dup2(unsigned int v){
  unsigned long long d;
  asm("mov.b64 %0, {%1, %1};" : "=l"(d) : "r"(v));
  return d;
}

// ---------------- main fused kernel ----------------
// k2 layout: [p][32] u64; half h uses slots h*16 + y (y=0..14), slot 15/31 = 0 pad
__global__ void __launch_bounds__(256, 4)
shconv_kernel(const float* __restrict__ x0, const float* __restrict__ x1,
              const float* __restrict__ x2, const float* __restrict__ x3,
              const int*  __restrict__ pidx, const float* __restrict__ kern,
              float* __restrict__ out)
{
  __shared__ int rowi[32];
  __shared__ __align__(16) unsigned long long k2[32*32];
  __shared__ __align__(16) float ysm[YROWS*CTOT];

  const int tid = threadIdx.x;
  const int bv  = blockIdx.x;

  if(tid < 32){
    int2 pr = ((const int2*)pidx)[(size_t)bv*PP + tid];
    rowi[tid] = pr.x * NN + pr.y;
  }
  const float* kb = kern + (size_t)bv * (PP*YROWS);
  for(int q = tid; q < 32*32; q += 256){
    int p = q >> 5, s = q & 31;
    int y = s & 15, h = s >> 4;
    int row = h*15 + y;
    float v = (y < 15) ? kb[p*YROWS + row] : 0.f;
    unsigned int u = __float_as_uint(v);
    k2[q] = ((unsigned long long)u << 32) | u;
  }
  __syncthreads();

  // ---- phase 1: y[30][256] = K[30x32] @ G[32x256] ----
  // thread = (half: 15 rows) x (cp: 2 channels)
  const int cpair = tid & 127;
  const int half  = tid >> 7;
  const int c = cpair * 2;
  const float* bp; int st;
  if(c < 16)       { bp = x0 + c;        st = 16;  }
  else if(c < 64)  { bp = x1 + (c-16);   st = 48;  }
  else if(c < 144) { bp = x2 + (c-64);   st = 80;  }
  else             { bp = x3 + (c-144);  st = 112; }

  unsigned long long acc[16];
  #pragma unroll
  for(int y = 0; y < 16; y++) acc[y] = 0ull;

  unsigned long long gv = *(const unsigned long long*)(bp + (size_t)rowi[0]*st);
  #pragma unroll 4
  for(int p = 0; p < PP; p++){
    unsigned long long nx = *(const unsigned long long*)(bp + (size_t)rowi[(p+1)&31]*st);
    const ulonglong2* kp = (const ulonglong2*)&k2[p*32 + half*16];
    #pragma unroll
    for(int y = 0; y < 8; y++){
      ulonglong2 kv = kp[y];
      acc[2*y]   = ffma2(kv.x, gv, acc[2*y]);
      acc[2*y+1] = ffma2(kv.y, gv, acc[2*y+1]);
    }
    gv = nx;
  }
  {
    const int rbase = half*15;
    #pragma unroll
    for(int y = 0; y < 15; y++)
      *(unsigned long long*)&ysm[(rbase+y)*CTOT + c] = acc[y];
  }
  __syncthreads();

  // ---- phase 2: sparse CG program ----
  for(int idx = tid; idx < 2664; idx += 256){
    unsigned long long h = __ldg(&g_items[idx]);
    int ybase = (int)(h & 0x1FFF);
    int cnt   = (int)((h >> 13) & 63);
    int start = (int)((h >> 19) & 4095);
    int J     = (int)((h >> 31) & 3);
    unsigned long long outb = h >> 33;

    unsigned long long a0 = 0ull, a1 = 0ull;
    const unsigned long long* tp = &g_terms[start];
    int t = 0;
    for(; t + 2 <= cnt; t += 2){
      unsigned long long t0 = __ldg(&tp[t]);
      unsigned long long t1 = __ldg(&tp[t+1]);
      unsigned long long y0 = *(const unsigned long long*)&ysm[ybase + (int)(t0 >> 32)];
      unsigned long long y1 = *(const unsigned long long*)&ysm[ybase + (int)(t1 >> 32)];
      a0 = ffma2(dup2((unsigned int)t0), y0, a0);
      a1 = ffma2(dup2((unsigned int)t1), y1, a1);
    }
    if(t < cnt){
      unsigned long long t0 = __ldg(&tp[t]);
      unsigned long long y0 = *(const unsigned long long*)&ysm[ybase + (int)(t0 >> 32)];
      a0 = ffma2(dup2((unsigned int)t0), y0, a0);
    }
    unsigned long long r = fadd2(a0, a1);
    size_t o = (size_t)outb + (size_t)bv * (size_t)c_bvmul[J];
    *(unsigned long long*)(out + o) = r;
  }
}

// ---------------- launch ----------------
extern "C" void kernel_launch(void* const* d_in, const int* in_sizes, int n_in,
                              void* d_out, int out_size)
{
  const float* x0   = (const float*)d_in[0];
  const float* x1   = (const float*)d_in[1];
  const float* x2   = (const float*)d_in[2];
  const float* x3   = (const float*)d_in[3];
  const int*   pidx = (const int*)  d_in[4];
  const float* kern = (const float*)d_in[5];
  float* out = (float*)d_out;

  cg_setup_kernel<<<27, 256>>>();
  table_build<<<1, 256>>>();
  shconv_kernel<<<NBV, 256>>>(x0, x1, x2, x3, pidx, kern, out);
}

// round 4
// speedup vs baseline: 3.3417x; 1.3232x over previous
#include <cuda_runtime.h>
#include <cstdint>
#include <math.h>
#include <string.h>

// ---------------- problem constants ----------------
#define BB 4
#define NN 4096
#define PP 32
#define CTOT 256
#define YROWS 30
#define NBV (BB*2048)

// ---------------- device tables (filled via async memcpy each launch) -----
__device__ unsigned long long g_terms[3400];
__device__ unsigned long long g_items[2664];

// ---------------- shared host/device layout tables ----------------
#define N_TRI 27
static const int h_tri[N_TRI][4] = {
  {1,1,0,0},{1,1,1,9},{1,1,2,36},
  {1,2,1,81},{1,2,2,126},{1,2,3,201},
  {1,3,2,306},{1,3,3,411},
  {2,1,1,558},{2,1,2,603},{2,1,3,678},
  {2,2,0,783},{2,2,1,808},{2,2,2,883},{2,2,3,1008},
  {2,3,1,1183},{2,3,2,1288},{2,3,3,1463},
  {3,1,2,1708},{3,1,3,1813},
  {3,2,1,1960},{3,2,2,2065},{3,2,3,2240},
  {3,3,0,2485},{3,3,1,2534},{3,3,2,2681},{3,3,3,2926}
};

struct HSeg { int kind, j, l, cstart, cgoff; };
static const HSeg h_segs[4][11] = {
  { {0,0,0,0,0},{2,1,1,64,0},{2,2,2,112,783},{2,3,3,144,2485},
    {0,0,0,0,0},{0,0,0,0,0},{0,0,0,0,0},{0,0,0,0,0},{0,0,0,0,0},{0,0,0,0,0},{0,0,0,0,0} },
  { {0,1,0,0,0},{1,0,1,48,0},{2,1,1,112,9},{2,2,1,160,558},{2,1,2,192,81},
    {2,2,2,240,808},{2,3,2,272,1960},{2,2,3,288,1183},{2,3,3,320,2534},
    {0,0,0,0,0},{0,0,0,0,0} },
  { {0,2,0,0,0},{1,0,2,32,0},{2,1,1,96,36},{2,2,1,144,603},{2,3,1,176,1708},
    {2,1,2,192,126},{2,2,2,240,883},{2,3,2,272,2065},{2,1,3,288,306},
    {2,2,3,336,1288},{2,3,3,368,2681} },
  { {0,3,0,0,0},{1,0,3,16,0},{2,2,1,80,678},{2,3,1,112,1813},{2,1,2,128,201},
    {2,2,2,176,1008},{2,3,2,208,2240},{2,1,3,224,411},{2,2,3,272,1463},
    {2,3,3,304,2926},{0,0,0,0,0} }
};

static const unsigned char h_lut[4][24] = {
  {0,0,0,0,1,1,1,2,2,3, 0,0,0,0,0,0,0,0,0,0,0,0,0,0},
  {0,0,0,1,1,1,1,2,2,2,3,3,4,4,4,5,5,6,7,7,8, 0,0,0},
  {0,0,1,1,1,1,2,2,2,3,3,4,5,5,5,6,6,7,8,8,8,9,9,10},
  {0,1,1,1,1,2,2,3,4,4,4,5,5,6,7,7,7,8,8,9, 0,0,0,0}
};

static const int h_yoff[4] = {0,4,13,23};
static const int h_coff[4] = {0,16,64,144};
static const int h_chj[4]  = {160,336,384,320};
static const unsigned long long h_outoff[4] = {0ull, 1310720ull, 9568256ull, 25296896ull};
static const int h_jb[4] = {0,1,4,9};

__constant__ int c_bvmul[4] = {160, 1008, 1920, 2240};

// ---------------- host-side CG + table computation ----------------
static double hfact(int n){
  static const double f[21] = {
    1.0,1.0,2.0,6.0,24.0,120.0,720.0,5040.0,40320.0,362880.0,3628800.0,
    39916800.0,479001600.0,6227020800.0,87178291200.0,1307674368000.0,
    20922789888000.0,355687428096000.0,6402373705728000.0,
    121645100408832000.0,2432902008176640000.0 };
  return f[n];
}

static double h_su2cg(int j1,int m1,int j2,int m2,int j3,int m3){
  if(m1+m2 != m3) return 0.0;
  int vmin = -j1+j2+m3; if(-j1+m1 > vmin) vmin = -j1+m1; if(0 > vmin) vmin = 0;
  int vmax = j2+j3+m1; if(j3-j1+j2 < vmax) vmax = j3-j1+j2; if(j3+m3 < vmax) vmax = j3+m3;
  double Cc = sqrt((double)(2*j3+1)*hfact(j3+j1-j2)*hfact(j3-j1+j2)*hfact(j1+j2-j3)
                   *hfact(j3+m3)*hfact(j3-m3)
                   /(hfact(j1+j2+j3+1)*hfact(j1-m1)*hfact(j1+m1)*hfact(j2-m2)*hfact(j2+m2)));
  double S = 0.0;
  for(int v=vmin; v<=vmax; v++){
    double t = hfact(j2+j3+m1-v)*hfact(j1-m1+v)
             /(hfact(v)*hfact(j3-j1+j2-v)*hfact(j3+m3-v)*hfact(v+j1-j2-m3));
    S += ((v+j2+m2)&1) ? -t : t;
  }
  return Cc*S;
}

struct Cpx { double re, im; };
static inline Cpx cmul(Cpx a, Cpx b){ Cpx r; r.re=a.re*b.re-a.im*b.im; r.im=a.re*b.im+a.im*b.re; return r; }

static void h_buildQ(int l, Cpx* q){
  int n = 2*l+1;
  for(int a=0;a<n*n;a++){ q[a].re=0.0; q[a].im=0.0; }
  const double s2 = 0.70710678118654752440;
  for(int m=-l;m<0;m++){
    q[(l+m)*n + (l-m)].re = s2;
    q[(l+m)*n + (l+m)].im = -s2;
  }
  q[l*n+l].re = 1.0;
  for(int m=1;m<=l;m++){
    double sg = (m&1)? -1.0 : 1.0;
    q[(l+m)*n + (l+m)].re = sg*s2;
    q[(l+m)*n + (l-m)].im = sg*s2;
  }
  int r = l & 3;
  Cpx ph = (r==0)? Cpx{1,0} : (r==1)? Cpx{0,-1} : (r==2)? Cpx{-1,0} : Cpx{0,1};
  for(int a=0;a<n*n;a++) q[a] = cmul(ph, q[a]);
}

static float h_cg[3269];
static unsigned long long h_terms[3400];
static unsigned long long h_items[2664];
static int h_lstart[160], h_lcount[160];

static void build_tables(){
  // ---- dense CG table ----
  for(int t = 0; t < N_TRI; t++){
    int j = h_tri[t][0], l = h_tri[t][1], J = h_tri[t][2], off = h_tri[t][3];
    int nj = 2*j+1, nl = 2*l+1, nJ = 2*J+1;
    Cpx Q1[49], Q2[49], Q3[49];
    h_buildQ(j, Q1); h_buildQ(l, Q2); h_buildQ(J, Q3);
    double Cs[343];
    for(int i=0;i<nj;i++)
      for(int k=0;k<nl;k++)
        for(int n=0;n<nJ;n++)
          Cs[(i*nl+k)*nJ+n] = h_su2cg(j, i-j, l, k-l, J, n-J);
    for(int jj=0;jj<nj;jj++)
      for(int ll=0;ll<nl;ll++)
        for(int mm=0;mm<nJ;mm++){
          double sx = 0.0;
          for(int i=0;i<nj;i++){
            Cpx a = Q1[i*nj+jj];
            for(int k=0;k<nl;k++){
              int n = i + k - j - l + J;
              if(n < 0 || n >= nJ) continue;
              double c = Cs[(i*nl+k)*nJ + n];
              if(c == 0.0) continue;
              Cpx b  = Q2[k*nl+ll];
              Cpx q3 = Q3[n*nJ+mm];
              Cpx ab = cmul(a, b);
              sx += c * (ab.re*q3.re + ab.im*q3.im);   // Re(ab * conj(q3))
            }
          }
          h_cg[off + (jj*nl+ll)*nJ + mm] = (float)sx;
        }
  }

  // ---- pass A: list counts ----
  for(int lid = 0; lid < 157; lid++){
    if(lid < 125){
      int k = lid, t = 0;
      for(; t < N_TRI; t++){ int sz = 2*h_tri[t][2]+1; if(k < sz) break; k -= sz; }
      int j = h_tri[t][0], l = h_tri[t][1], J = h_tri[t][2], off = h_tri[t][3];
      int nl = 2*l+1, nJ = 2*J+1, p = k;
      int cnt = 0;
      for(int n = 0; n <= 2*j; n++)
        for(int m = 0; m < nl; m++)
          if(fabsf(h_cg[off + (n*nl+m)*nJ + p]) > 1e-6f) cnt++;
      h_lcount[lid] = cnt;
    } else h_lcount[lid] = 1;
  }
  { int s = 0; for(int i = 0; i < 157; i++){ h_lstart[i] = s; s += h_lcount[i]; } }

  // ---- pass B: terms ----
  for(int lid = 0; lid < 157; lid++){
    int st = h_lstart[lid];
    if(lid < 125){
      int k = lid, t = 0;
      for(; t < N_TRI; t++){ int sz = 2*h_tri[t][2]+1; if(k < sz) break; k -= sz; }
      int j = h_tri[t][0], l = h_tri[t][1], J = h_tri[t][2], off = h_tri[t][3];
      int nl = 2*l+1, nJ = 2*J+1, p = k;
      for(int n = 0; n <= 2*j; n++)
        for(int m = 0; m < nl; m++){
          float c = h_cg[off + (n*nl+m)*nJ + p];
          if(fabsf(c) > 1e-6f){
            int delta = n*(4-j)*CTOT + m*16;
            unsigned u; memcpy(&u, &c, 4);
            h_terms[st++] = ((unsigned long long)(unsigned)delta << 32) | u;
          }
        }
    } else if(lid < 141){
      int k = lid - 125, j = 0;
      while(k >= 2*j+1){ k -= 2*j+1; j++; }
      int delta = k*(4-j)*CTOT;
      float one = 1.0f; unsigned u; memcpy(&u, &one, 4);
      h_terms[st] = ((unsigned long long)(unsigned)delta << 32) | u;
    } else {
      int k = lid - 141, l = 0;
      while(k >= 2*l+1){ k -= 2*l+1; l++; }
      int delta = k*16;
      float one = 1.0f; unsigned u; memcpy(&u, &one, 4);
      h_terms[st] = ((unsigned long long)(unsigned)delta << 32) | u;
    }
  }

  // ---- pass C: item headers ----
  for(int idx = 0; idx < 2664; idx++){
    int J, p, cp;
    if(idx < 80)        { J=0; p=0; cp=idx; }
    else if(idx < 584)  { J=1; int r=idx-80;   p=r/168; cp=r-p*168; }
    else if(idx < 1544) { J=2; int r=idx-584;  p=r/192; cp=r-p*192; }
    else                { J=3; int r=idx-1544; p=r/160; cp=r-p*160; }
    int chan = cp << 1;
    HSeg s = h_segs[J][h_lut[J][chan>>4]];
    int local = chan - s.cstart;
    int i2 = local >> 4;
    int ch = local & 15;

    int lid;
    if(s.kind == 0)      lid = 125 + h_jb[s.j] + p;
    else if(s.kind == 1) lid = 141 + h_jb[s.l] + p;
    else {
      int t = 0;
      for(; t < N_TRI; t++) if(h_tri[t][3] == s.cgoff) break;
      int base = 0;
      for(int q = 0; q < t; q++) base += 2*h_tri[q][2]+1;
      lid = base + p;
    }
    int ybase = (h_yoff[s.j] + i2)*CTOT + h_coff[s.l] + ch;
    int start = h_lstart[lid];
    int cnt   = h_lcount[lid];
    unsigned long long outb = h_outoff[J] + (unsigned long long)p*h_chj[J] + chan;
    unsigned long long h = (unsigned long long)ybase
                         | ((unsigned long long)cnt   << 13)
                         | ((unsigned long long)start << 19)
                         | ((unsigned long long)J     << 31)
                         | (outb << 33);
    h_items[idx] = h;
  }
}

// ---------------- packed f32x2 ops ----------------
__device__ __forceinline__ unsigned long long ffma2(unsigned long long a,
                                                    unsigned long long b,
                                                    unsigned long long c){
  unsigned long long d;
  asm("fma.rn.f32x2 %0, %1, %2, %3;" : "=l"(d) : "l"(a), "l"(b), "l"(c));
  return d;
}
__device__ __forceinline__ unsigned long long fadd2(unsigned long long a,
                                                    unsigned long long b){
  unsigned long long d;
  asm("add.rn.f32x2 %0, %1, %2;" : "=l"(d) : "l"(a), "l"(b));
  return d;
}
__device__ __forceinline__ unsigned long long dup2(unsigned int v){
  unsigned long long d;
  asm("mov.b64 %0, {%1, %1};" : "=l"(d) : "r"(v));
  return d;
}
__device__ __forceinline__ void stcs64(float* p, unsigned long long v){
  asm volatile("st.global.cs.b64 [%0], %1;" :: "l"(p), "l"(v) : "memory");
}

// ---------------- main fused kernel ----------------
// 384 threads: (grp: 3 groups of 10 rows) x (cpair: 128 channel pairs)
// k2 layout: [p][36] u64; group g at slots g*12 + y (y=0..9), rest zero pad
__global__ void __launch_bounds__(384, 3)
shconv_kernel(const float* __restrict__ x0, const float* __restrict__ x1,
              const float* __restrict__ x2, const float* __restrict__ x3,
              const int*  __restrict__ pidx, const float* __restrict__ kern,
              float* __restrict__ out)
{
  __shared__ int rowi[32];
  __shared__ __align__(16) unsigned long long k2[32*36];
  __shared__ __align__(16) float ysm[YROWS*CTOT];

  const int tid = threadIdx.x;
  const int bv  = blockIdx.x;

  if(tid < 32){
    int2 pr = ((const int2*)pidx)[(size_t)bv*PP + tid];
    rowi[tid] = pr.x * NN + pr.y;
  }
  const float* kb = kern + (size_t)bv * (PP*YROWS);
  for(int q = tid; q < 32*36; q += 384){
    int p = q / 36, s = q - p*36;
    int g = s / 12, y = s - g*12;
    int row = g*10 + y;
    float v = (y < 10) ? kb[p*YROWS + row] : 0.f;
    unsigned int u = __float_as_uint(v);
    k2[q] = ((unsigned long long)u << 32) | u;
  }
  __syncthreads();

  // ---- phase 1: y[30][256] = K[30x32] @ G[32x256] ----
  const int cpair = tid & 127;
  const int grp   = tid >> 7;          // 0..2
  const int c = cpair * 2;
  const float* bp; int st;
  if(c < 16)       { bp = x0 + c;        st = 16;  }
  else if(c < 64)  { bp = x1 + (c-16);   st = 48;  }
  else if(c < 144) { bp = x2 + (c-64);   st = 80;  }
  else             { bp = x3 + (c-144);  st = 112; }

  unsigned long long acc[10];
  #pragma unroll
  for(int y = 0; y < 10; y++) acc[y] = 0ull;

  unsigned long long gv = *(const unsigned long long*)(bp + (size_t)rowi[0]*st);
  #pragma unroll 4
  for(int p = 0; p < PP; p++){
    unsigned long long nx = *(const unsigned long long*)(bp + (size_t)rowi[(p+1)&31]*st);
    const ulonglong2* kp = (const ulonglong2*)&k2[p*36 + grp*12];
    #pragma unroll
    for(int y = 0; y < 5; y++){
      ulonglong2 kv = kp[y];
      acc[2*y]   = ffma2(kv.x, gv, acc[2*y]);
      acc[2*y+1] = ffma2(kv.y, gv, acc[2*y+1]);
    }
    gv = nx;
  }
  {
    const int rbase = grp*10;
    #pragma unroll
    for(int y = 0; y < 10; y++)
      *(unsigned long long*)&ysm[(rbase+y)*CTOT + c] = acc[y];
  }
  __syncthreads();

  // ---- phase 2: sparse CG program ----
  for(int idx = tid; idx < 2664; idx += 384){
    unsigned long long h = __ldg(&g_items[idx]);
    int ybase = (int)(h & 0x1FFF);
    int cnt   = (int)((h >> 13) & 63);
    int start = (int)((h >> 19) & 4095);
    int J     = (int)((h >> 31) & 3);
    unsigned long long outb = h >> 33;

    unsigned long long a0 = 0ull, a1 = 0ull;
    const unsigned long long* tp = &g_terms[start];
    int t = 0;
    for(; t + 2 <= cnt; t += 2){
      unsigned long long t0 = __ldg(&tp[t]);
      unsigned long long t1 = __ldg(&tp[t+1]);
      unsigned long long y0 = *(const unsigned long long*)&ysm[ybase + (int)(t0 >> 32)];
      unsigned long long y1 = *(const unsigned long long*)&ysm[ybase + (int)(t1 >> 32)];
      a0 = ffma2(dup2((unsigned int)t0), y0, a0);
      a1 = ffma2(dup2((unsigned int)t1), y1, a1);
    }
    if(t < cnt){
      unsigned long long t0 = __ldg(&tp[t]);
      unsigned long long y0 = *(const unsigned long long*)&ysm[ybase + (int)(t0 >> 32)];
      a0 = ffma2(dup2((unsigned int)t0), y0, a0);
    }
    unsigned long long r = fadd2(a0, a1);
    size_t o = (size_t)outb + (size_t)bv * (size_t)c_bvmul[J];
    stcs64(out + o, r);
  }
}

// ---------------- launch ----------------
extern "C" void kernel_launch(void* const* d_in, const int* in_sizes, int n_in,
                              void* d_out, int out_size)
{
  const float* x0   = (const float*)d_in[0];
  const float* x1   = (const float*)d_in[1];
  const float* x2   = (const float*)d_in[2];
  const float* x3   = (const float*)d_in[3];
  const int*   pidx = (const int*)  d_in[4];
  const float* kern = (const float*)d_in[5];
  float* out = (float*)d_out;

  build_tables();   // pure host computation into static buffers

  cudaMemcpyToSymbolAsync(g_terms, h_terms, sizeof(h_terms), 0,
                          cudaMemcpyHostToDevice, 0);
  cudaMemcpyToSymbolAsync(g_items, h_items, sizeof(h_items), 0,
                          cudaMemcpyHostToDevice, 0);

  shconv_kernel<<<NBV, 384>>>(x0, x1, x2, x3, pidx, kern, out);
}

// round 5
// speedup vs baseline: 3.7003x; 1.1073x over previous
#include <cuda_runtime.h>
#include <cstdint>
#include <math.h>
#include <string.h>

// ---------------- problem constants ----------------
#define BB 4
#define NN 4096
#define PP 32
#define CTOT 256
#define YROWS 30
#define NBV (BB*2048)

// ---------------- device tables (filled via async memcpy each launch) -----
__device__ unsigned long long g_terms[3400];
__device__ unsigned long long g_items[1332];

// ---------------- shared host/device layout tables ----------------
#define N_TRI 27
static const int h_tri[N_TRI][4] = {
  {1,1,0,0},{1,1,1,9},{1,1,2,36},
  {1,2,1,81},{1,2,2,126},{1,2,3,201},
  {1,3,2,306},{1,3,3,411},
  {2,1,1,558},{2,1,2,603},{2,1,3,678},
  {2,2,0,783},{2,2,1,808},{2,2,2,883},{2,2,3,1008},
  {2,3,1,1183},{2,3,2,1288},{2,3,3,1463},
  {3,1,2,1708},{3,1,3,1813},
  {3,2,1,1960},{3,2,2,2065},{3,2,3,2240},
  {3,3,0,2485},{3,3,1,2534},{3,3,2,2681},{3,3,3,2926}
};

struct HSeg { int kind, j, l, cstart, cgoff; };
static const HSeg h_segs[4][11] = {
  { {0,0,0,0,0},{2,1,1,64,0},{2,2,2,112,783},{2,3,3,144,2485},
    {0,0,0,0,0},{0,0,0,0,0},{0,0,0,0,0},{0,0,0,0,0},{0,0,0,0,0},{0,0,0,0,0},{0,0,0,0,0} },
  { {0,1,0,0,0},{1,0,1,48,0},{2,1,1,112,9},{2,2,1,160,558},{2,1,2,192,81},
    {2,2,2,240,808},{2,3,2,272,1960},{2,2,3,288,1183},{2,3,3,320,2534},
    {0,0,0,0,0},{0,0,0,0,0} },
  { {0,2,0,0,0},{1,0,2,32,0},{2,1,1,96,36},{2,2,1,144,603},{2,3,1,176,1708},
    {2,1,2,192,126},{2,2,2,240,883},{2,3,2,272,2065},{2,1,3,288,306},
    {2,2,3,336,1288},{2,3,3,368,2681} },
  { {0,3,0,0,0},{1,0,3,16,0},{2,2,1,80,678},{2,3,1,112,1813},{2,1,2,128,201},
    {2,2,2,176,1008},{2,3,2,208,2240},{2,1,3,224,411},{2,2,3,272,1463},
    {2,3,3,304,2926},{0,0,0,0,0} }
};

static const unsigned char h_lut[4][24] = {
  {0,0,0,0,1,1,1,2,2,3, 0,0,0,0,0,0,0,0,0,0,0,0,0,0},
  {0,0,0,1,1,1,1,2,2,2,3,3,4,4,4,5,5,6,7,7,8, 0,0,0},
  {0,0,1,1,1,1,2,2,2,3,3,4,5,5,5,6,6,7,8,8,8,9,9,10},
  {0,1,1,1,1,2,2,3,4,4,4,5,5,6,7,7,7,8,8,9, 0,0,0,0}
};

static const int h_yoff[4] = {0,4,13,23};
static const int h_coff[4] = {0,16,64,144};
static const int h_chj[4]  = {160,336,384,320};
static const unsigned long long h_outoff[4] = {0ull, 1310720ull, 9568256ull, 25296896ull};
static const int h_jb[4] = {0,1,4,9};

__constant__ int c_bvmul[4] = {160, 1008, 1920, 2240};

// ---------------- host-side CG + table computation ----------------
static double hfact(int n){
  static const double f[21] = {
    1.0,1.0,2.0,6.0,24.0,120.0,720.0,5040.0,40320.0,362880.0,3628800.0,
    39916800.0,479001600.0,6227020800.0,87178291200.0,1307674368000.0,
    20922789888000.0,355687428096000.0,6402373705728000.0,
    121645100408832000.0,2432902008176640000.0 };
  return f[n];
}

static double h_su2cg(int j1,int m1,int j2,int m2,int j3,int m3){
  if(m1+m2 != m3) return 0.0;
  int vmin = -j1+j2+m3; if(-j1+m1 > vmin) vmin = -j1+m1; if(0 > vmin) vmin = 0;
  int vmax = j2+j3+m1; if(j3-j1+j2 < vmax) vmax = j3-j1+j2; if(j3+m3 < vmax) vmax = j3+m3;
  double Cc = sqrt((double)(2*j3+1)*hfact(j3+j1-j2)*hfact(j3-j1+j2)*hfact(j1+j2-j3)
                   *hfact(j3+m3)*hfact(j3-m3)
                   /(hfact(j1+j2+j3+1)*hfact(j1-m1)*hfact(j1+m1)*hfact(j2-m2)*hfact(j2+m2)));
  double S = 0.0;
  for(int v=vmin; v<=vmax; v++){
    double t = hfact(j2+j3+m1-v)*hfact(j1-m1+v)
             /(hfact(v)*hfact(j3-j1+j2-v)*hfact(j3+m3-v)*hfact(v+j1-j2-m3));
    S += ((v+j2+m2)&1) ? -t : t;
  }
  return Cc*S;
}

struct Cpx { double re, im; };
static inline Cpx cmul(Cpx a, Cpx b){ Cpx r; r.re=a.re*b.re-a.im*b.im; r.im=a.re*b.im+a.im*b.re; return r; }

static void h_buildQ(int l, Cpx* q){
  int n = 2*l+1;
  for(int a=0;a<n*n;a++){ q[a].re=0.0; q[a].im=0.0; }
  const double s2 = 0.70710678118654752440;
  for(int m=-l;m<0;m++){
    q[(l+m)*n + (l-m)].re = s2;
    q[(l+m)*n + (l+m)].im = -s2;
  }
  q[l*n+l].re = 1.0;
  for(int m=1;m<=l;m++){
    double sg = (m&1)? -1.0 : 1.0;
    q[(l+m)*n + (l+m)].re = sg*s2;
    q[(l+m)*n + (l-m)].im = sg*s2;
  }
  int r = l & 3;
  Cpx ph = (r==0)? Cpx{1,0} : (r==1)? Cpx{0,-1} : (r==2)? Cpx{-1,0} : Cpx{0,1};
  for(int a=0;a<n*n;a++) q[a] = cmul(ph, q[a]);
}

static float h_cg[3269];
static unsigned long long h_terms[3400];
static unsigned long long h_items[1332];
static int h_lstart[160], h_lcount[160];

static void build_tables(){
  // ---- dense CG table ----
  for(int t = 0; t < N_TRI; t++){
    int j = h_tri[t][0], l = h_tri[t][1], J = h_tri[t][2], off = h_tri[t][3];
    int nj = 2*j+1, nl = 2*l+1, nJ = 2*J+1;
    Cpx Q1[49], Q2[49], Q3[49];
    h_buildQ(j, Q1); h_buildQ(l, Q2); h_buildQ(J, Q3);
    double Cs[343];
    for(int i=0;i<nj;i++)
      for(int k=0;k<nl;k++)
        for(int n=0;n<nJ;n++)
          Cs[(i*nl+k)*nJ+n] = h_su2cg(j, i-j, l, k-l, J, n-J);
    for(int jj=0;jj<nj;jj++)
      for(int ll=0;ll<nl;ll++)
        for(int mm=0;mm<nJ;mm++){
          double sx = 0.0;
          for(int i=0;i<nj;i++){
            Cpx a = Q1[i*nj+jj];
            for(int k=0;k<nl;k++){
              int n = i + k - j - l + J;
              if(n < 0 || n >= nJ) continue;
              double c = Cs[(i*nl+k)*nJ + n];
              if(c == 0.0) continue;
              Cpx b  = Q2[k*nl+ll];
              Cpx q3 = Q3[n*nJ+mm];
              Cpx ab = cmul(a, b);
              sx += c * (ab.re*q3.re + ab.im*q3.im);   // Re(ab * conj(q3))
            }
          }
          h_cg[off + (jj*nl+ll)*nJ + mm] = (float)sx;
        }
  }

  // ---- pass A: list counts ----
  for(int lid = 0; lid < 157; lid++){
    if(lid < 125){
      int k = lid, t = 0;
      for(; t < N_TRI; t++){ int sz = 2*h_tri[t][2]+1; if(k < sz) break; k -= sz; }
      int j = h_tri[t][0], l = h_tri[t][1], J = h_tri[t][2], off = h_tri[t][3];
      int nl = 2*l+1, nJ = 2*J+1, p = k;
      int cnt = 0;
      for(int n = 0; n <= 2*j; n++)
        for(int m = 0; m < nl; m++)
          if(fabsf(h_cg[off + (n*nl+m)*nJ + p]) > 1e-6f) cnt++;
      h_lcount[lid] = cnt;
    } else h_lcount[lid] = 1;
  }
  { int s = 0; for(int i = 0; i < 157; i++){ h_lstart[i] = s; s += h_lcount[i]; } }

  // ---- pass B: terms ----
  for(int lid = 0; lid < 157; lid++){
    int st = h_lstart[lid];
    if(lid < 125){
      int k = lid, t = 0;
      for(; t < N_TRI; t++){ int sz = 2*h_tri[t][2]+1; if(k < sz) break; k -= sz; }
      int j = h_tri[t][0], l = h_tri[t][1], J = h_tri[t][2], off = h_tri[t][3];
      int nl = 2*l+1, nJ = 2*J+1, p = k;
      for(int n = 0; n <= 2*j; n++)
        for(int m = 0; m < nl; m++){
          float c = h_cg[off + (n*nl+m)*nJ + p];
          if(fabsf(c) > 1e-6f){
            int delta = n*(4-j)*CTOT + m*16;
            unsigned u; memcpy(&u, &c, 4);
            h_terms[st++] = ((unsigned long long)(unsigned)delta << 32) | u;
          }
        }
    } else if(lid < 141){
      int k = lid - 125, j = 0;
      while(k >= 2*j+1){ k -= 2*j+1; j++; }
      int delta = k*(4-j)*CTOT;
      float one = 1.0f; unsigned u; memcpy(&u, &one, 4);
      h_terms[st] = ((unsigned long long)(unsigned)delta << 32) | u;
    } else {
      int k = lid - 141, l = 0;
      while(k >= 2*l+1){ k -= 2*l+1; l++; }
      int delta = k*16;
      float one = 1.0f; unsigned u; memcpy(&u, &one, 4);
      h_terms[st] = ((unsigned long long)(unsigned)delta << 32) | u;
    }
  }

  // ---- pass C: item headers (4 channels per item) ----
  for(int idx = 0; idx < 1332; idx++){
    int J, p, cp;
    if(idx < 40)        { J=0; p=0; cp=idx; }
    else if(idx < 292)  { J=1; int r=idx-40;  p=r/84; cp=r-p*84; }
    else if(idx < 772)  { J=2; int r=idx-292; p=r/96; cp=r-p*96; }
    else                { J=3; int r=idx-772; p=r/80; cp=r-p*80; }
    int chan = cp << 2;
    HSeg s = h_segs[J][h_lut[J][chan>>4]];
    int local = chan - s.cstart;
    int i2 = local >> 4;
    int ch = local & 15;

    int lid;
    if(s.kind == 0)      lid = 125 + h_jb[s.j] + p;
    else if(s.kind == 1) lid = 141 + h_jb[s.l] + p;
    else {
      int t = 0;
      for(; t < N_TRI; t++) if(h_tri[t][3] == s.cgoff) break;
      int base = 0;
      for(int q = 0; q < t; q++) base += 2*h_tri[q][2]+1;
      lid = base + p;
    }
    int ybase = (h_yoff[s.j] + i2)*CTOT + h_coff[s.l] + ch;
    int start = h_lstart[lid];
    int cnt   = h_lcount[lid];
    unsigned long long outb = h_outoff[J] + (unsigned long long)p*h_chj[J] + chan;
    unsigned long long h = (unsigned long long)ybase
                         | ((unsigned long long)cnt   << 13)
                         | ((unsigned long long)start << 19)
                         | ((unsigned long long)J     << 31)
                         | (outb << 33);
    h_items[idx] = h;
  }
}

// ---------------- packed f32x2 ops ----------------
__device__ __forceinline__ unsigned long long ffma2(unsigned long long a,
                                                    unsigned long long b,
                                                    unsigned long long c){
  unsigned long long d;
  asm("fma.rn.f32x2 %0, %1, %2, %3;" : "=l"(d) : "l"(a), "l"(b), "l"(c));
  return d;
}
__device__ __forceinline__ unsigned long long fadd2(unsigned long long a,
                                                    unsigned long long b){
  unsigned long long d;
  asm("add.rn.f32x2 %0, %1, %2;" : "=l"(d) : "l"(a), "l"(b));
  return d;
}
__device__ __forceinline__ unsigned long long dup2(unsigned int v){
  unsigned long long d;
  asm("mov.b64 %0, {%1, %1};" : "=l"(d) : "r"(v));
  return d;
}
__device__ __forceinline__ void stcs128(float* p, unsigned long long a,
                                        unsigned long long b){
  asm volatile("st.global.cs.v2.u64 [%0], {%1, %2};" :: "l"(p), "l"(a), "l"(b) : "memory");
}

// ---------------- main fused kernel ----------------
// 192 threads: (grp: 3 groups of 10 rows) x (cquad: 64 quads of 4 channels)
// k2 layout: [p][36] u64; group g at slots g*12 + y (y=0..9), rest zero pad
__global__ void __launch_bounds__(192, 4)
shconv_kernel(const float* __restrict__ x0, const float* __restrict__ x1,
              const float* __restrict__ x2, const float* __restrict__ x3,
              const int*  __restrict__ pidx, const float* __restrict__ kern,
              float* __restrict__ out)
{
  __shared__ int rowi[32];
  __shared__ __align__(16) unsigned long long k2[32*36];
  __shared__ __align__(16) float ysm[YROWS*CTOT];

  const int tid = threadIdx.x;
  const int bv  = blockIdx.x;

  if(tid < 32){
    int2 pr = ((const int2*)pidx)[(size_t)bv*PP + tid];
    rowi[tid] = pr.x * NN + pr.y;
  }
  const float* kb = kern + (size_t)bv * (PP*YROWS);
  for(int q = tid; q < 32*36; q += 192){
    int p = q / 36, s = q - p*36;
    int g = s / 12, y = s - g*12;
    int row = g*10 + y;
    float v = (y < 10) ? kb[p*YROWS + row] : 0.f;
    unsigned int u = __float_as_uint(v);
    k2[q] = ((unsigned long long)u << 32) | u;
  }
  __syncthreads();

  // ---- phase 1: y[30][256] = K[30x32] @ G[32x256], 4 ch x 10 rows/thread ----
  const int cquad = tid & 63;
  const int grp   = tid >> 6;          // 0..2
  const int c = cquad * 4;
  const float* bp; int st;
  if(c < 16)       { bp = x0 + c;        st = 16;  }
  else if(c < 64)  { bp = x1 + (c-16);   st = 48;  }
  else if(c < 144) { bp = x2 + (c-64);   st = 80;  }
  else             { bp = x3 + (c-144);  st = 112; }

  ulonglong2 acc[10];
  #pragma unroll
  for(int y = 0; y < 10; y++){ acc[y].x = 0ull; acc[y].y = 0ull; }

  ulonglong2 gv = *(const ulonglong2*)(bp + (size_t)rowi[0]*st);
  #pragma unroll 4
  for(int p = 0; p < PP; p++){
    ulonglong2 nx = *(const ulonglong2*)(bp + (size_t)rowi[(p+1)&31]*st);
    const ulonglong2* kp = (const ulonglong2*)&k2[p*36 + grp*12];
    #pragma unroll
    for(int y = 0; y < 5; y++){
      ulonglong2 kv = kp[y];
      acc[2*y].x   = ffma2(kv.x, gv.x, acc[2*y].x);
      acc[2*y].y   = ffma2(kv.x, gv.y, acc[2*y].y);
      acc[2*y+1].x = ffma2(kv.y, gv.x, acc[2*y+1].x);
      acc[2*y+1].y = ffma2(kv.y, gv.y, acc[2*y+1].y);
    }
    gv = nx;
  }
  {
    const int rbase = grp*10;
    #pragma unroll
    for(int y = 0; y < 10; y++)
      *(ulonglong2*)&ysm[(rbase+y)*CTOT + c] = acc[y];
  }
  __syncthreads();

  // ---- phase 2: sparse CG program, 4 output channels per item ----
  for(int idx = tid; idx < 1332; idx += 192){
    unsigned long long h = __ldg(&g_items[idx]);
    int ybase = (int)(h & 0x1FFF);
    int cnt   = (int)((h >> 13) & 63);
    int start = (int)((h >> 19) & 4095);
    int J     = (int)((h >> 31) & 3);
    unsigned long long outb = h >> 33;

    unsigned long long a0 = 0ull, a1 = 0ull, b0 = 0ull, b1 = 0ull;
    const unsigned long long* tp = &g_terms[start];
    int t = 0;
    for(; t + 2 <= cnt; t += 2){
      unsigned long long t0 = __ldg(&tp[t]);
      unsigned long long t1 = __ldg(&tp[t+1]);
      ulonglong2 y0 = *(const ulonglong2*)&ysm[ybase + (int)(t0 >> 32)];
      ulonglong2 y1 = *(const ulonglong2*)&ysm[ybase + (int)(t1 >> 32)];
      unsigned long long c0 = dup2((unsigned int)t0);
      unsigned long long c1 = dup2((unsigned int)t1);
      a0 = ffma2(c0, y0.x, a0); a1 = ffma2(c0, y0.y, a1);
      b0 = ffma2(c1, y1.x, b0); b1 = ffma2(c1, y1.y, b1);
    }
    if(t < cnt){
      unsigned long long t0 = __ldg(&tp[t]);
      ulonglong2 y0 = *(const ulonglong2*)&ysm[ybase + (int)(t0 >> 32)];
      unsigned long long c0 = dup2((unsigned int)t0);
      a0 = ffma2(c0, y0.x, a0); a1 = ffma2(c0, y0.y, a1);
    }
    a0 = fadd2(a0, b0);
    a1 = fadd2(a1, b1);
    size_t o = (size_t)outb + (size_t)bv * (size_t)c_bvmul[J];
    stcs128(out + o, a0, a1);
  }
}

// ---------------- launch ----------------
extern "C" void kernel_launch(void* const* d_in, const int* in_sizes, int n_in,
                              void* d_out, int out_size)
{
  const float* x0   = (const float*)d_in[0];
  const float* x1   = (const float*)d_in[1];
  const float* x2   = (const float*)d_in[2];
  const float* x3   = (const float*)d_in[3];
  const int*   pidx = (const int*)  d_in[4];
  const float* kern = (const float*)d_in[5];
  float* out = (float*)d_out;

  build_tables();   // pure host computation into static buffers

  cudaMemcpyToSymbolAsync(g_terms, h_terms, sizeof(h_terms), 0,
                          cudaMemcpyHostToDevice, 0);
  cudaMemcpyToSymbolAsync(g_items, h_items, sizeof(h_items), 0,
                          cudaMemcpyHostToDevice, 0);

  shconv_kernel<<<NBV, 192>>>(x0, x1, x2, x3, pidx, kern, out);
}

// round 6
// speedup vs baseline: 4.2441x; 1.1470x over previous
#include <cuda_runtime.h>
#include <cstdint>
#include <math.h>
#include <string.h>

// ---------------- problem constants ----------------
#define BB 4
#define NN 4096
#define PP 32
#define CTOT 256
#define YROWS 30
#define NBV (BB*2048)

// ---------------- device tables (filled via async memcpy each launch) -----
__device__ unsigned long long g_terms[3400];
__device__ unsigned long long g_items[1332];

// ---------------- shared host/device layout tables ----------------
#define N_TRI 27
static const int h_tri[N_TRI][4] = {
  {1,1,0,0},{1,1,1,9},{1,1,2,36},
  {1,2,1,81},{1,2,2,126},{1,2,3,201},
  {1,3,2,306},{1,3,3,411},
  {2,1,1,558},{2,1,2,603},{2,1,3,678},
  {2,2,0,783},{2,2,1,808},{2,2,2,883},{2,2,3,1008},
  {2,3,1,1183},{2,3,2,1288},{2,3,3,1463},
  {3,1,2,1708},{3,1,3,1813},
  {3,2,1,1960},{3,2,2,2065},{3,2,3,2240},
  {3,3,0,2485},{3,3,1,2534},{3,3,2,2681},{3,3,3,2926}
};

struct HSeg { int kind, j, l, cstart, cgoff; };
static const HSeg h_segs[4][11] = {
  { {0,0,0,0,0},{2,1,1,64,0},{2,2,2,112,783},{2,3,3,144,2485},
    {0,0,0,0,0},{0,0,0,0,0},{0,0,0,0,0},{0,0,0,0,0},{0,0,0,0,0},{0,0,0,0,0},{0,0,0,0,0} },
  { {0,1,0,0,0},{1,0,1,48,0},{2,1,1,112,9},{2,2,1,160,558},{2,1,2,192,81},
    {2,2,2,240,808},{2,3,2,272,1960},{2,2,3,288,1183},{2,3,3,320,2534},
    {0,0,0,0,0},{0,0,0,0,0} },
  { {0,2,0,0,0},{1,0,2,32,0},{2,1,1,96,36},{2,2,1,144,603},{2,3,1,176,1708},
    {2,1,2,192,126},{2,2,2,240,883},{2,3,2,272,2065},{2,1,3,288,306},
    {2,2,3,336,1288},{2,3,3,368,2681} },
  { {0,3,0,0,0},{1,0,3,16,0},{2,2,1,80,678},{2,3,1,112,1813},{2,1,2,128,201},
    {2,2,2,176,1008},{2,3,2,208,2240},{2,1,3,224,411},{2,2,3,272,1463},
    {2,3,3,304,2926},{0,0,0,0,0} }
};

static const unsigned char h_lut[4][24] = {
  {0,0,0,0,1,1,1,2,2,3, 0,0,0,0,0,0,0,0,0,0,0,0,0,0},
  {0,0,0,1,1,1,1,2,2,2,3,3,4,4,4,5,5,6,7,7,8, 0,0,0},
  {0,0,1,1,1,1,2,2,2,3,3,4,5,5,5,6,6,7,8,8,8,9,9,10},
  {0,1,1,1,1,2,2,3,4,4,4,5,5,6,7,7,7,8,8,9, 0,0,0,0}
};

static const int h_yoff[4] = {0,4,13,23};
static const int h_coff[4] = {0,16,64,144};
static const int h_chj[4]  = {160,336,384,320};
static const unsigned long long h_outoff[4] = {0ull, 1310720ull, 9568256ull, 25296896ull};
static const int h_jb[4] = {0,1,4,9};

__constant__ int c_bvmul[4] = {160, 1008, 1920, 2240};

// ---------------- host-side CG + table computation ----------------
static double hfact(int n){
  static const double f[21] = {
    1.0,1.0,2.0,6.0,24.0,120.0,720.0,5040.0,40320.0,362880.0,3628800.0,
    39916800.0,479001600.0,6227020800.0,87178291200.0,1307674368000.0,
    20922789888000.0,355687428096000.0,6402373705728000.0,
    121645100408832000.0,2432902008176640000.0 };
  return f[n];
}

static double h_su2cg(int j1,int m1,int j2,int m2,int j3,int m3){
  if(m1+m2 != m3) return 0.0;
  int vmin = -j1+j2+m3; if(-j1+m1 > vmin) vmin = -j1+m1; if(0 > vmin) vmin = 0;
  int vmax = j2+j3+m1; if(j3-j1+j2 < vmax) vmax = j3-j1+j2; if(j3+m3 < vmax) vmax = j3+m3;
  double Cc = sqrt((double)(2*j3+1)*hfact(j3+j1-j2)*hfact(j3-j1+j2)*hfact(j1+j2-j3)
                   *hfact(j3+m3)*hfact(j3-m3)
                   /(hfact(j1+j2+j3+1)*hfact(j1-m1)*hfact(j1+m1)*hfact(j2-m2)*hfact(j2+m2)));
  double S = 0.0;
  for(int v=vmin; v<=vmax; v++){
    double t = hfact(j2+j3+m1-v)*hfact(j1-m1+v)
             /(hfact(v)*hfact(j3-j1+j2-v)*hfact(j3+m3-v)*hfact(v+j1-j2-m3));
    S += ((v+j2+m2)&1) ? -t : t;
  }
  return Cc*S;
}

struct Cpx { double re, im; };
static inline Cpx cmul(Cpx a, Cpx b){ Cpx r; r.re=a.re*b.re-a.im*b.im; r.im=a.re*b.im+a.im*b.re; return r; }

static void h_buildQ(int l, Cpx* q){
  int n = 2*l+1;
  for(int a=0;a<n*n;a++){ q[a].re=0.0; q[a].im=0.0; }
  const double s2 = 0.70710678118654752440;
  for(int m=-l;m<0;m++){
    q[(l+m)*n + (l-m)].re = s2;
    q[(l+m)*n + (l+m)].im = -s2;
  }
  q[l*n+l].re = 1.0;
  for(int m=1;m<=l;m++){
    double sg = (m&1)? -1.0 : 1.0;
    q[(l+m)*n + (l+m)].re = sg*s2;
    q[(l+m)*n + (l-m)].im = sg*s2;
  }
  int r = l & 3;
  Cpx ph = (r==0)? Cpx{1,0} : (r==1)? Cpx{0,-1} : (r==2)? Cpx{-1,0} : Cpx{0,1};
  for(int a=0;a<n*n;a++) q[a] = cmul(ph, q[a]);
}

static float h_cg[3269];
static unsigned long long h_terms[3400];
static unsigned long long h_items[1332];
static int h_lstart[160], h_lcount[160];

static void build_tables(){
  for(int t = 0; t < N_TRI; t++){
    int j = h_tri[t][0], l = h_tri[t][1], J = h_tri[t][2], off = h_tri[t][3];
    int nj = 2*j+1, nl = 2*l+1, nJ = 2*J+1;
    Cpx Q1[49], Q2[49], Q3[49];
    h_buildQ(j, Q1); h_buildQ(l, Q2); h_buildQ(J, Q3);
    double Cs[343];
    for(int i=0;i<nj;i++)
      for(int k=0;k<nl;k++)
        for(int n=0;n<nJ;n++)
          Cs[(i*nl+k)*nJ+n] = h_su2cg(j, i-j, l, k-l, J, n-J);
    for(int jj=0;jj<nj;jj++)
      for(int ll=0;ll<nl;ll++)
        for(int mm=0;mm<nJ;mm++){
          double sx = 0.0;
          for(int i=0;i<nj;i++){
            Cpx a = Q1[i*nj+jj];
            for(int k=0;k<nl;k++){
              int n = i + k - j - l + J;
              if(n < 0 || n >= nJ) continue;
              double c = Cs[(i*nl+k)*nJ + n];
              if(c == 0.0) continue;
              Cpx b  = Q2[k*nl+ll];
              Cpx q3 = Q3[n*nJ+mm];
              Cpx ab = cmul(a, b);
              sx += c * (ab.re*q3.re + ab.im*q3.im);
            }
          }
          h_cg[off + (jj*nl+ll)*nJ + mm] = (float)sx;
        }
  }

  for(int lid = 0; lid < 157; lid++){
    if(lid < 125){
      int k = lid, t = 0;
      for(; t < N_TRI; t++){ int sz = 2*h_tri[t][2]+1; if(k < sz) break; k -= sz; }
      int j = h_tri[t][0], l = h_tri[t][1], J = h_tri[t][2], off = h_tri[t][3];
      int nl = 2*l+1, nJ = 2*J+1, p = k;
      int cnt = 0;
      for(int n = 0; n <= 2*j; n++)
        for(int m = 0; m < nl; m++)
          if(fabsf(h_cg[off + (n*nl+m)*nJ + p]) > 1e-6f) cnt++;
      h_lcount[lid] = cnt;
    } else h_lcount[lid] = 1;
  }
  { int s = 0; for(int i = 0; i < 157; i++){ h_lstart[i] = s; s += h_lcount[i]; } }

  for(int lid = 0; lid < 157; lid++){
    int st = h_lstart[lid];
    if(lid < 125){
      int k = lid, t = 0;
      for(; t < N_TRI; t++){ int sz = 2*h_tri[t][2]+1; if(k < sz) break; k -= sz; }
      int j = h_tri[t][0], l = h_tri[t][1], J = h_tri[t][2], off = h_tri[t][3];
      int nl = 2*l+1, nJ = 2*J+1, p = k;
      for(int n = 0; n <= 2*j; n++)
        for(int m = 0; m < nl; m++){
          float c = h_cg[off + (n*nl+m)*nJ + p];
          if(fabsf(c) > 1e-6f){
            int delta = n*(4-j)*CTOT + m*16;
            unsigned u; memcpy(&u, &c, 4);
            h_terms[st++] = ((unsigned long long)(unsigned)delta << 32) | u;
          }
        }
    } else if(lid < 141){
      int k = lid - 125, j = 0;
      while(k >= 2*j+1){ k -= 2*j+1; j++; }
      int delta = k*(4-j)*CTOT;
      float one = 1.0f; unsigned u; memcpy(&u, &one, 4);
      h_terms[st] = ((unsigned long long)(unsigned)delta << 32) | u;
    } else {
      int k = lid - 141, l = 0;
      while(k >= 2*l+1){ k -= 2*l+1; l++; }
      int delta = k*16;
      float one = 1.0f; unsigned u; memcpy(&u, &one, 4);
      h_terms[st] = ((unsigned long long)(unsigned)delta << 32) | u;
    }
  }

  for(int idx = 0; idx < 1332; idx++){
    int J, p, cp;
    if(idx < 40)        { J=0; p=0; cp=idx; }
    else if(idx < 292)  { J=1; int r=idx-40;  p=r/84; cp=r-p*84; }
    else if(idx < 772)  { J=2; int r=idx-292; p=r/96; cp=r-p*96; }
    else                { J=3; int r=idx-772; p=r/80; cp=r-p*80; }
    int chan = cp << 2;
    HSeg s = h_segs[J][h_lut[J][chan>>4]];
    int local = chan - s.cstart;
    int i2 = local >> 4;
    int ch = local & 15;

    int lid;
    if(s.kind == 0)      lid = 125 + h_jb[s.j] + p;
    else if(s.kind == 1) lid = 141 + h_jb[s.l] + p;
    else {
      int t = 0;
      for(; t < N_TRI; t++) if(h_tri[t][3] == s.cgoff) break;
      int base = 0;
      for(int q = 0; q < t; q++) base += 2*h_tri[q][2]+1;
      lid = base + p;
    }
    int ybase = (h_yoff[s.j] + i2)*CTOT + h_coff[s.l] + ch;
    int start = h_lstart[lid];
    int cnt   = h_lcount[lid];
    unsigned long long outb = h_outoff[J] + (unsigned long long)p*h_chj[J] + chan;
    unsigned long long h = (unsigned long long)ybase
                         | ((unsigned long long)cnt   << 13)
                         | ((unsigned long long)start << 19)
                         | ((unsigned long long)J     << 31)
                         | (outb << 33);
    h_items[idx] = h;
  }
}

// ---------------- packed f32x2 ops / asm helpers ----------------
__device__ __forceinline__ unsigned long long ffma2(unsigned long long a,
                                                    unsigned long long b,
                                                    unsigned long long c){
  unsigned long long d;
  asm("fma.rn.f32x2 %0, %1, %2, %3;" : "=l"(d) : "l"(a), "l"(b), "l"(c));
  return d;
}
__device__ __forceinline__ unsigned long long fadd2(unsigned long long a,
                                                    unsigned long long b){
  unsigned long long d;
  asm("add.rn.f32x2 %0, %1, %2;" : "=l"(d) : "l"(a), "l"(b));
  return d;
}
__device__ __forceinline__ unsigned long long dup2(unsigned int v){
  unsigned long long d;
  asm("mov.b64 %0, {%1, %1};" : "=l"(d) : "r"(v));
  return d;
}
__device__ __forceinline__ void stcs128(float* p, unsigned long long a,
                                        unsigned long long b){
  asm volatile("st.global.cs.v2.u64 [%0], {%1, %2};" :: "l"(p), "l"(a), "l"(b) : "memory");
}
__device__ __forceinline__ unsigned int smem_u32(const void* p){
  unsigned int a;
  asm("{ .reg .u64 t; cvta.to.shared.u64 t, %1; cvt.u32.u64 %0, t; }"
      : "=r"(a) : "l"(p));
  return a;
}
__device__ __forceinline__ void cpa16(unsigned int saddr, const void* gaddr){
  asm volatile("cp.async.cg.shared.global [%0], [%1], 16;" :: "r"(saddr), "l"(gaddr));
}

// ---------------- main fused kernel ----------------
// 192 threads: (grp: 3 groups of 10 rows) x (cquad: 64 quads of 4 channels)
// gy: union of G tile [32p x 256ch] (phase 1 input) and ysm [30 x 256] (phase 2)
__global__ void __launch_bounds__(192, 5)
shconv_kernel(const float* __restrict__ x0, const float* __restrict__ x1,
              const float* __restrict__ x2, const float* __restrict__ x3,
              const int*  __restrict__ pidx, const float* __restrict__ kern,
              float* __restrict__ out)
{
  __shared__ int rowi[32];
  __shared__ __align__(16) float gy[PP*CTOT];             // 32KB (ysm uses 30KB of it)
  __shared__ __align__(16) unsigned long long k2[32*36];  // 9KB

  const int tid = threadIdx.x;
  const int bv  = blockIdx.x;

  if(tid < 32){
    int2 pr = ((const int2*)pidx)[(size_t)bv*PP + tid];
    rowi[tid] = pr.x * NN + pr.y;
  }
  __syncthreads();

  // ---- stage G[32][256] into smem via cp.async (each 16B chunk once) ----
  {
    unsigned int gybase = smem_u32(gy);
    #pragma unroll
    for(int k = 0; k < 11; k++){
      int idx = tid + k*192;
      if(k == 10 && idx >= 2048) break;
      int row = idx >> 6;          // patch p
      int col = idx & 63;          // 16B chunk within row
      int c = col * 4;
      const float* bp; int st;
      if(c < 16)       { bp = x0 + c;        st = 16;  }
      else if(c < 64)  { bp = x1 + (c-16);   st = 48;  }
      else if(c < 144) { bp = x2 + (c-64);   st = 80;  }
      else             { bp = x3 + (c-144);  st = 112; }
      cpa16(gybase + idx*16, bp + (size_t)rowi[row]*st);
    }
    asm volatile("cp.async.commit_group;");
  }

  // ---- fill k2 while cp.async is in flight ----
  const float* kb = kern + (size_t)bv * (PP*YROWS);
  #pragma unroll
  for(int i = 0; i < 6; i++){
    int q = tid + i*192;
    int p = q / 36, s = q - p*36;
    int g = s / 12, y = s - g*12;
    int row = g*10 + y;
    float v = (y < 10) ? kb[p*YROWS + row] : 0.f;
    unsigned int u = __float_as_uint(v);
    k2[q] = ((unsigned long long)u << 32) | u;
  }
  asm volatile("cp.async.wait_group 0;");
  __syncthreads();

  // ---- phase 1: y[30][256] = K[30x32] @ G[32x256], all operands in smem ----
  const int cquad = tid & 63;
  const int grp   = tid >> 6;          // 0..2
  const int c = cquad * 4;

  ulonglong2 acc[10];
  #pragma unroll
  for(int y = 0; y < 10; y++){ acc[y].x = 0ull; acc[y].y = 0ull; }

  const float* gp = &gy[c];
  #pragma unroll 4
  for(int p = 0; p < PP; p++){
    ulonglong2 gv = *(const ulonglong2*)(gp + p*CTOT);
    const ulonglong2* kp = (const ulonglong2*)&k2[p*36 + grp*12];
    #pragma unroll
    for(int y = 0; y < 5; y++){
      ulonglong2 kv = kp[y];
      acc[2*y].x   = ffma2(kv.x, gv.x, acc[2*y].x);
      acc[2*y].y   = ffma2(kv.x, gv.y, acc[2*y].y);
      acc[2*y+1].x = ffma2(kv.y, gv.x, acc[2*y+1].x);
      acc[2*y+1].y = ffma2(kv.y, gv.y, acc[2*y+1].y);
    }
  }
  __syncthreads();   // all G reads done before overwriting gy with y

  {
    const int rbase = grp*10;
    #pragma unroll
    for(int y = 0; y < 10; y++)
      *(ulonglong2*)&gy[(rbase+y)*CTOT + c] = acc[y];
  }
  __syncthreads();

  // ---- phase 2: sparse CG program, 4 output channels per item ----
  for(int idx = tid; idx < 1332; idx += 192){
    unsigned long long h = __ldg(&g_items[idx]);
    int ybase = (int)(h & 0x1FFF);
    int cnt   = (int)((h >> 13) & 63);
    int start = (int)((h >> 19) & 4095);
    int J     = (int)((h >> 31) & 3);
    unsigned long long outb = h >> 33;

    unsigned long long a0 = 0ull, a1 = 0ull, b0 = 0ull, b1 = 0ull;
    const unsigned long long* tp = &g_terms[start];
    int t = 0;
    for(; t + 2 <= cnt; t += 2){
      unsigned long long t0 = __ldg(&tp[t]);
      unsigned long long t1 = __ldg(&tp[t+1]);
      ulonglong2 y0 = *(const ulonglong2*)&gy[ybase + (int)(t0 >> 32)];
      ulonglong2 y1 = *(const ulonglong2*)&gy[ybase + (int)(t1 >> 32)];
      unsigned long long c0 = dup2((unsigned int)t0);
      unsigned long long c1 = dup2((unsigned int)t1);
      a0 = ffma2(c0, y0.x, a0); a1 = ffma2(c0, y0.y, a1);
      b0 = ffma2(c1, y1.x, b0); b1 = ffma2(c1, y1.y, b1);
    }
    if(t < cnt){
      unsigned long long t0 = __ldg(&tp[t]);
      ulonglong2 y0 = *(const ulonglong2*)&gy[ybase + (int)(t0 >> 32)];
      unsigned long long c0 = dup2((unsigned int)t0);
      a0 = ffma2(c0, y0.x, a0); a1 = ffma2(c0, y0.y, a1);
    }
    a0 = fadd2(a0, b0);
    a1 = fadd2(a1, b1);
    size_t o = (size_t)outb + (size_t)bv * (size_t)c_bvmul[J];
    stcs128(out + o, a0, a1);
  }
}

// ---------------- launch ----------------
extern "C" void kernel_launch(void* const* d_in, const int* in_sizes, int n_in,
                              void* d_out, int out_size)
{
  const float* x0   = (const float*)d_in[0];
  const float* x1   = (const float*)d_in[1];
  const float* x2   = (const float*)d_in[2];
  const float* x3   = (const float*)d_in[3];
  const int*   pidx = (const int*)  d_in[4];
  const float* kern = (const float*)d_in[5];
  float* out = (float*)d_out;

  build_tables();

  cudaMemcpyToSymbolAsync(g_terms, h_terms, sizeof(h_terms), 0,
                          cudaMemcpyHostToDevice, 0);
  cudaMemcpyToSymbolAsync(g_items, h_items, sizeof(h_items), 0,
                          cudaMemcpyHostToDevice, 0);

  shconv_kernel<<<NBV, 192>>>(x0, x1, x2, x3, pidx, kern, out);
}